// round 1
// baseline (speedup 1.0000x reference)
#include <cuda_runtime.h>
#include <math.h>

#define N_NODES 4096
#define N_EDGES 16384
#define N_GRAPHS 16
#define HDIM 128
#define LN_EPS 1e-5f

// Padded contraction dims (multiple of 8 for the GEMM)
// layer1: KI=128*3=384, +3 bias rows = 387 -> pad 392
// layer2/3: KI=128*128=16384, +128 bias rows = 16512 (already %8==0)
static const int KP_L1 = 392;
static const int KP_L23 = 16512;

// ---------------- device scratch (no allocations allowed) ----------------
__device__ float d_M[(size_t)N_NODES * 16512];   // 270 MB scatter target
__device__ float d_W2p[16512 * HDIM];            // permuted w2 (+b2 rows)
__device__ float d_Hc[N_EDGES * HDIM];           // edge MLP output
__device__ float d_XA[N_NODES * HDIM];
__device__ float d_XB[N_NODES * HDIM];
__device__ float d_AGG[N_NODES * HDIM];
__device__ int d_cnt[N_NODES];
__device__ int d_off[N_NODES];
__device__ int d_cur[N_NODES];
__device__ int d_eperm[N_EDGES];
__device__ int d_gcnt[N_GRAPHS];

// ---------------- CSR build ----------------
__global__ void k_zero_counters() {
    int i = blockIdx.x * blockDim.x + threadIdx.x;
    if (i < N_NODES) { d_cnt[i] = 0; d_cur[i] = 0; }
    if (i < N_GRAPHS) d_gcnt[i] = 0;
}

__global__ void k_hist(const int* __restrict__ ei, const int* __restrict__ batch) {
    int e = blockIdx.x * blockDim.x + threadIdx.x;
    if (e < N_EDGES) atomicAdd(&d_cnt[ei[N_EDGES + e]], 1);
    if (e < N_NODES) atomicAdd(&d_gcnt[batch[e]], 1);
}

__global__ void k_scan() {
    __shared__ int part[1024];
    int t = threadIdx.x;
    int v0 = d_cnt[t*4], v1 = d_cnt[t*4+1], v2 = d_cnt[t*4+2], v3 = d_cnt[t*4+3];
    int s = v0 + v1 + v2 + v3;
    part[t] = s;
    __syncthreads();
    for (int d = 1; d < 1024; d <<= 1) {
        int add = (t >= d) ? part[t - d] : 0;
        __syncthreads();
        part[t] += add;
        __syncthreads();
    }
    int excl = part[t] - s;
    d_off[t*4]   = excl;
    d_off[t*4+1] = excl + v0;
    d_off[t*4+2] = excl + v0 + v1;
    d_off[t*4+3] = excl + v0 + v1 + v2;
}

__global__ void k_fill(const int* __restrict__ ei) {
    int e = blockIdx.x * blockDim.x + threadIdx.x;
    if (e < N_EDGES) {
        int d = ei[N_EDGES + e];
        int p = atomicAdd(&d_cur[d], 1);
        d_eperm[d_off[d] + p] = e;
    }
}

// ---------------- edge MLP: h = relu(ea @ w1 + b1) ----------------
__global__ void k_edge_mlp(const float* __restrict__ ea,
                           const float* __restrict__ w1,
                           const float* __restrict__ b1) {
    int e = blockIdx.x;
    int o = threadIdx.x;
    float4 a = *(const float4*)&ea[e * 4];
    float v = b1[o] + a.x * w1[o] + a.y * w1[128 + o] + a.z * w1[256 + o] + a.w * w1[384 + o];
    d_Hc[e * HDIM + o] = fmaxf(v, 0.f);
}

// ---------------- permute w2 into [KP, H]; append b2 bias rows ----------------
__global__ void k_permw2(const float* __restrict__ w2, const float* __restrict__ b2,
                         int in_c, int KP) {
    int idx = blockIdx.x * blockDim.x + threadIdx.x;
    if (idx >= KP * HDIM) return;
    int j = idx >> 7, o = idx & 127;
    int KI = 128 * in_c;
    float v = 0.f;
    if (j < KI) {
        int k = j / in_c, i = j - k * in_c;
        v = w2[k * (in_c * HDIM) + i * HDIM + o];
    } else if (j < KI + in_c) {
        int i = j - KI;
        v = b2[i * HDIM + o];
    }
    d_W2p[idx] = v;
}

// ---------------- scatter: M[n] = sum_e h[e] (x) x[src_e], + bias-rows ----------------
template <int INC>
__global__ void k_scatter(const float* __restrict__ X, const int* __restrict__ ei) {
    constexpr int KI = 128 * INC;
    constexpr int KIext = KI + INC;
    constexpr int KP = (KIext + 7) & ~7;
    __shared__ float sh_h[32 * 128];
    __shared__ float sh_x[32 * INC];
    __shared__ int sh_e[32];

    int n = blockIdx.x;
    int deg = d_cnt[n];
    int off = d_off[n];
    int tid = threadIdx.x;

    int base = 0;
    while (true) {
        int c = deg - base; if (c > 32) c = 32; if (c < 0) c = 0;
        if (tid < c) sh_e[tid] = d_eperm[off + base + tid];
        __syncthreads();
        for (int t = tid; t < c * 128; t += 256) {
            int dd = t >> 7, k = t & 127;
            sh_h[dd * 128 + k] = d_Hc[sh_e[dd] * HDIM + k];
        }
        for (int t = tid; t < c * INC; t += 256) {
            int dd = t / INC, i = t - dd * INC;
            int s = ei[sh_e[dd]];
            sh_x[dd * INC + i] = X[s * INC + i];
        }
        __syncthreads();
        for (int j = tid; j < KP; j += 256) {
            float v = 0.f;
            if (j < KI) {
                int k = j / INC, i = j - k * INC;
                for (int dd = 0; dd < c; dd++)
                    v += sh_h[dd * 128 + k] * sh_x[dd * INC + i];
            } else if (j < KIext) {
                int i = j - KI;
                for (int dd = 0; dd < c; dd++)
                    v += sh_x[dd * INC + i];
            }
            size_t idx = (size_t)n * KP + j;
            if (base == 0) d_M[idx] = v;
            else           d_M[idx] += v;
        }
        __syncthreads();
        base += 32;
        if (base >= deg) break;
    }
}

// ---------------- zero AGG ----------------
__global__ void k_zero_agg() {
    int i = blockIdx.x * blockDim.x + threadIdx.x;
    if (i < N_NODES * HDIM) d_AGG[i] = 0.f;
}

// ---------------- split-K fp32 GEMM: AGG += M[:,kb:ke] @ W2p[kb:ke,:] ----------------
__global__ __launch_bounds__(256) void k_gemm(int K, int chunk) {
    __shared__ float As[8 * 128];
    __shared__ float Bs[8 * 128];
    int row0 = blockIdx.x * 128;
    int kb = blockIdx.y * chunk;
    int ke = kb + chunk; if (ke > K) ke = K;
    int tid = threadIdx.x;
    int tr = tid >> 4, tc = tid & 15;
    float acc[8][8];
#pragma unroll
    for (int m = 0; m < 8; m++)
#pragma unroll
        for (int n = 0; n < 8; n++) acc[m][n] = 0.f;

    int ar = tid >> 1, ac = (tid & 1) * 4;
    int br = tid >> 5, bc = (tid & 31) * 4;

    for (int k0 = kb; k0 < ke; k0 += 8) {
        float4 av = *(const float4*)&d_M[(size_t)(row0 + ar) * K + k0 + ac];
        float4 bv = *(const float4*)&d_W2p[(k0 + br) * HDIM + bc];
        As[(ac + 0) * 128 + ar] = av.x;
        As[(ac + 1) * 128 + ar] = av.y;
        As[(ac + 2) * 128 + ar] = av.z;
        As[(ac + 3) * 128 + ar] = av.w;
        *(float4*)&Bs[br * 128 + bc] = bv;
        __syncthreads();
#pragma unroll
        for (int kk = 0; kk < 8; kk++) {
            float a[8], b[8];
#pragma unroll
            for (int m = 0; m < 8; m++) a[m] = As[kk * 128 + tr * 8 + m];
#pragma unroll
            for (int n = 0; n < 8; n++) b[n] = Bs[kk * 128 + tc * 8 + n];
#pragma unroll
            for (int m = 0; m < 8; m++)
#pragma unroll
                for (int n = 0; n < 8; n++)
                    acc[m][n] += a[m] * b[n];
        }
        __syncthreads();
    }
#pragma unroll
    for (int m = 0; m < 8; m++) {
        int r = row0 + tr * 8 + m;
#pragma unroll
        for (int n = 0; n < 8; n++)
            atomicAdd(&d_AGG[r * HDIM + tc * 8 + n], acc[m][n]);
    }
}

// ---------------- combine: agg/cnt + x@root + bias -> LN -> activation ----------------
// ACT: 0=relu, 1=elu, 2=leaky_relu(0.01)
template <int INC, int ACT>
__global__ void k_combine(const float* __restrict__ Xin,
                          const float* __restrict__ root,
                          const float* __restrict__ bias,
                          const float* __restrict__ lng,
                          const float* __restrict__ lnb,
                          float* __restrict__ Xout) {
    __shared__ float shx[INC];
    __shared__ float red[4];
    int n = blockIdx.x;
    int o = threadIdx.x;
    for (int i = o; i < INC; i += 128) shx[i] = Xin[n * INC + i];
    __syncthreads();

    float r = bias[o];
#pragma unroll 4
    for (int i = 0; i < INC; i++) r += shx[i] * root[i * HDIM + o];

    float cnt = (float)max(d_cnt[n], 1);
    float pre = d_AGG[n * HDIM + o] / cnt + r;

    // block sum (128 threads, 4 warps)
    float v = pre;
    for (int s = 16; s; s >>= 1) v += __shfl_xor_sync(0xffffffffu, v, s);
    if ((o & 31) == 0) red[o >> 5] = v;
    __syncthreads();
    float mean = (red[0] + red[1] + red[2] + red[3]) * (1.f / 128.f);
    __syncthreads();

    float cen = pre - mean;
    float v2 = cen * cen;
    for (int s = 16; s; s >>= 1) v2 += __shfl_xor_sync(0xffffffffu, v2, s);
    if ((o & 31) == 0) red[o >> 5] = v2;
    __syncthreads();
    float var = (red[0] + red[1] + red[2] + red[3]) * (1.f / 128.f);

    float y = cen * rsqrtf(var + LN_EPS) * lng[o] + lnb[o];
    if (ACT == 0)      y = fmaxf(y, 0.f);
    else if (ACT == 1) y = (y > 0.f) ? y : expm1f(y);
    else               y = (y >= 0.f) ? y : 0.01f * y;
    Xout[n * HDIM + o] = y;
}

// ---------------- pool (mean + max per graph) + final linear ----------------
__global__ void k_pool(const float* __restrict__ X,
                       const float* __restrict__ ct,
                       const float* __restrict__ ls,
                       const float* __restrict__ lw,
                       const float* __restrict__ lb,
                       float* __restrict__ out) {
    __shared__ float cat[261];
    int g = blockIdx.x;
    int o = threadIdx.x;
    int start = 0;
    for (int q = 0; q < g; q++) start += d_gcnt[q];
    int c = d_gcnt[g];
    float s = 0.f, mx = -INFINITY;
    for (int t = 0; t < c; t++) {
        float v = X[(size_t)(start + t) * HDIM + o];
        s += v;
        mx = fmaxf(mx, v);
    }
    cat[o]       = s / fmaxf((float)c, 1.f);
    cat[128 + o] = (c > 0) ? mx : 0.f;
    if (o < 4)  cat[256 + o] = ct[g * 4 + o];
    if (o == 4) cat[260] = ls[g];
    __syncthreads();
    if (o < 2) {
        float acc = lb[o];
        for (int j = 0; j < 261; j++) acc += cat[j] * lw[j * 2 + o];
        out[g * 2 + o] = acc;
    }
}

// ---------------- launch ----------------
extern "C" void kernel_launch(void* const* d_in, const int* in_sizes, int n_in,
                              void* d_out, int out_size) {
    const float* x     = (const float*)d_in[0];
    const int*   ei    = (const int*)  d_in[1];
    const float* ea    = (const float*)d_in[2];
    const int*   batch = (const int*)  d_in[3];
    const float* ct    = (const float*)d_in[4];
    const float* ls    = (const float*)d_in[5];

    const float* w1[3]   = {(const float*)d_in[6],  (const float*)d_in[12], (const float*)d_in[18]};
    const float* b1[3]   = {(const float*)d_in[7],  (const float*)d_in[13], (const float*)d_in[19]};
    const float* w2[3]   = {(const float*)d_in[8],  (const float*)d_in[14], (const float*)d_in[20]};
    const float* b2[3]   = {(const float*)d_in[9],  (const float*)d_in[15], (const float*)d_in[21]};
    const float* root[3] = {(const float*)d_in[10], (const float*)d_in[16], (const float*)d_in[22]};
    const float* bias[3] = {(const float*)d_in[11], (const float*)d_in[17], (const float*)d_in[23]};

    const float* lng[3] = {(const float*)d_in[24], (const float*)d_in[26], (const float*)d_in[28]};
    const float* lnb[3] = {(const float*)d_in[25], (const float*)d_in[27], (const float*)d_in[29]};
    const float* lw = (const float*)d_in[30];
    const float* lb = (const float*)d_in[31];
    float* out = (float*)d_out;

    float *pXA, *pXB;
    cudaGetSymbolAddress((void**)&pXA, d_XA);
    cudaGetSymbolAddress((void**)&pXB, d_XB);

    // CSR by dst + graph histogram (reused by all layers)
    k_zero_counters<<<16, 256>>>();
    k_hist<<<64, 256>>>(ei, batch);
    k_scan<<<1, 1024>>>();
    k_fill<<<64, 256>>>(ei);

    // ---- layer 1 (in_c = 3, relu) ----
    k_edge_mlp<<<N_EDGES, 128>>>(ea, w1[0], b1[0]);
    k_permw2<<<(KP_L1 * HDIM + 255) / 256, 256>>>(w2[0], b2[0], 3, KP_L1);
    k_scatter<3><<<N_NODES, 256>>>(x, ei);
    k_zero_agg<<<512, 1024>>>();
    k_gemm<<<dim3(32, 7), 256>>>(KP_L1, 56);
    k_combine<3, 0><<<N_NODES, 128>>>(x, root[0], bias[0], lng[0], lnb[0], pXA);

    // ---- layer 2 (in_c = 128, elu) ----
    k_edge_mlp<<<N_EDGES, 128>>>(ea, w1[1], b1[1]);
    k_permw2<<<(KP_L23 * HDIM + 255) / 256, 256>>>(w2[1], b2[1], 128, KP_L23);
    k_scatter<128><<<N_NODES, 256>>>(pXA, ei);
    k_zero_agg<<<512, 1024>>>();
    k_gemm<<<dim3(32, 16), 256>>>(KP_L23, 1032);
    k_combine<128, 1><<<N_NODES, 128>>>(pXA, root[1], bias[1], lng[1], lnb[1], pXB);

    // ---- layer 3 (in_c = 128, leaky_relu) ----
    k_edge_mlp<<<N_EDGES, 128>>>(ea, w1[2], b1[2]);
    k_permw2<<<(KP_L23 * HDIM + 255) / 256, 256>>>(w2[2], b2[2], 128, KP_L23);
    k_scatter<128><<<N_NODES, 256>>>(pXB, ei);
    k_zero_agg<<<512, 1024>>>();
    k_gemm<<<dim3(32, 16), 256>>>(KP_L23, 1032);
    k_combine<128, 2><<<N_NODES, 128>>>(pXB, root[2], bias[2], lng[2], lnb[2], pXA);

    // ---- pooling + final linear ----
    k_pool<<<N_GRAPHS, 128>>>(pXA, ct, ls, lw, lb, out);
}

// round 3
// speedup vs baseline: 1.7353x; 1.7353x over previous
#include <cuda_runtime.h>
#include <cuda_bf16.h>
#include <math.h>
#include <stdint.h>

#define N_NODES 4096
#define N_EDGES 16384
#define N_GRAPHS 16
#define HDIM 128
#define LN_EPS 1e-5f

// layer1: KI=128*3=384, +3 bias rows = 387 -> pad 392 (fp32 SIMT path, tiny)
// layer2/3: KI=128*128=16384, +128 bias rows = 16512 (HMMA path)
static const int KP_L1 = 392;
#define KP23 16512
#define NCHUNK 258          // 16512 / 64
#define KSPLIT 4

// ---------------- device scratch (no allocations allowed) ----------------
__device__ float d_M[(size_t)N_NODES * KP_L1];           // layer-1 fp32 M
__device__ float d_W2p[KP_L1 * HDIM];                    // layer-1 permuted w2
__device__ __nv_bfloat16 d_Ah[(size_t)N_NODES * KP23];   // hi(M) bf16
__device__ __nv_bfloat16 d_Al[(size_t)N_NODES * KP23];   // lo(M) bf16
__device__ __nv_bfloat16 d_Bh[(size_t)HDIM * KP23];      // hi(W2p^T) [o, j]
__device__ __nv_bfloat16 d_Bl[(size_t)HDIM * KP23];      // lo(W2p^T)
__device__ float d_Hc[N_EDGES * HDIM];
__device__ float d_XA[N_NODES * HDIM];
__device__ float d_XB[N_NODES * HDIM];
__device__ float d_AGG[N_NODES * HDIM];
__device__ int d_cnt[N_NODES];
__device__ int d_off[N_NODES];
__device__ int d_cur[N_NODES];
__device__ int d_eperm[N_EDGES];
__device__ int d_gcnt[N_GRAPHS];

// ---------------- PTX helpers (baseline ISA only — no sm_103a-only ops) ----------------
__device__ __forceinline__ uint32_t smem_u32(const void* p) {
    uint32_t a;
    asm("{ .reg .u64 t; cvta.to.shared.u64 t, %1; cvt.u32.u64 %0, t; }" : "=r"(a) : "l"(p));
    return a;
}
__device__ __forceinline__ void cpa16(uint32_t smem_addr, const void* g) {
    asm volatile("cp.async.cg.shared.global [%0], [%1], 16;" :: "r"(smem_addr), "l"(g));
}
#define CPA_COMMIT() asm volatile("cp.async.commit_group;" ::: "memory")
#define CPA_WAIT0()  asm volatile("cp.async.wait_group 0;" ::: "memory")
#define CPA_WAIT1()  asm volatile("cp.async.wait_group 1;" ::: "memory")

__device__ __forceinline__ void ldsm_x4(uint32_t* r, uint32_t addr) {
    asm volatile("ldmatrix.sync.aligned.m8n8.x4.shared.b16 {%0,%1,%2,%3}, [%4];"
                 : "=r"(r[0]), "=r"(r[1]), "=r"(r[2]), "=r"(r[3]) : "r"(addr));
}
__device__ __forceinline__ void mma_bf16(float* c, const uint32_t* a, uint32_t b0, uint32_t b1) {
    asm volatile("mma.sync.aligned.m16n8k16.row.col.f32.bf16.bf16.f32 "
                 "{%0,%1,%2,%3}, {%4,%5,%6,%7}, {%8,%9}, {%0,%1,%2,%3};"
                 : "+f"(c[0]), "+f"(c[1]), "+f"(c[2]), "+f"(c[3])
                 : "r"(a[0]), "r"(a[1]), "r"(a[2]), "r"(a[3]), "r"(b0), "r"(b1));
}
#define SW128(off) ((off) ^ (((off) >> 3) & 0x70))

// ---------------- CSR build ----------------
__global__ void k_zero_counters() {
    int i = blockIdx.x * blockDim.x + threadIdx.x;
    if (i < N_NODES) { d_cnt[i] = 0; d_cur[i] = 0; }
    if (i < N_GRAPHS) d_gcnt[i] = 0;
}

__global__ void k_hist(const int* __restrict__ ei, const int* __restrict__ batch) {
    int e = blockIdx.x * blockDim.x + threadIdx.x;
    if (e < N_EDGES) atomicAdd(&d_cnt[ei[N_EDGES + e]], 1);
    if (e < N_NODES) atomicAdd(&d_gcnt[batch[e]], 1);
}

__global__ void k_scan() {
    __shared__ int part[1024];
    int t = threadIdx.x;
    int v0 = d_cnt[t*4], v1 = d_cnt[t*4+1], v2 = d_cnt[t*4+2], v3 = d_cnt[t*4+3];
    int s = v0 + v1 + v2 + v3;
    part[t] = s;
    __syncthreads();
    for (int d = 1; d < 1024; d <<= 1) {
        int add = (t >= d) ? part[t - d] : 0;
        __syncthreads();
        part[t] += add;
        __syncthreads();
    }
    int excl = part[t] - s;
    d_off[t*4]   = excl;
    d_off[t*4+1] = excl + v0;
    d_off[t*4+2] = excl + v0 + v1;
    d_off[t*4+3] = excl + v0 + v1 + v2;
}

__global__ void k_fill(const int* __restrict__ ei) {
    int e = blockIdx.x * blockDim.x + threadIdx.x;
    if (e < N_EDGES) {
        int d = ei[N_EDGES + e];
        int p = atomicAdd(&d_cur[d], 1);
        d_eperm[d_off[d] + p] = e;
    }
}

// ---------------- edge MLP: h = relu(ea @ w1 + b1) ----------------
__global__ void k_edge_mlp(const float* __restrict__ ea,
                           const float* __restrict__ w1,
                           const float* __restrict__ b1) {
    int e = blockIdx.x;
    int o = threadIdx.x;
    float4 a = *(const float4*)&ea[e * 4];
    float v = b1[o] + a.x * w1[o] + a.y * w1[128 + o] + a.z * w1[256 + o] + a.w * w1[384 + o];
    d_Hc[e * HDIM + o] = fmaxf(v, 0.f);
}

// ---------------- layer-1 permuted w2 (fp32) ----------------
__global__ void k_permw2(const float* __restrict__ w2, const float* __restrict__ b2,
                         int in_c, int KP) {
    int idx = blockIdx.x * blockDim.x + threadIdx.x;
    if (idx >= KP * HDIM) return;
    int j = idx >> 7, o = idx & 127;
    int KI = 128 * in_c;
    float v = 0.f;
    if (j < KI) {
        int k = j / in_c, i = j - k * in_c;
        v = w2[k * (in_c * HDIM) + i * HDIM + o];
    } else if (j < KI + in_c) {
        int i = j - KI;
        v = b2[i * HDIM + o];
    }
    d_W2p[idx] = v;
}

// ---------------- layer-2/3 B matrix: [o, j] bf16 hi/lo (transposed w2 + b2 rows) ----------------
__global__ void k_permw2_bf16(const float* __restrict__ w2, const float* __restrict__ b2) {
    int idx = blockIdx.x * blockDim.x + threadIdx.x;
    if (idx >= HDIM * KP23) return;
    int o = idx / KP23, j = idx - o * KP23;
    float v;
    if (j < 16384) {
        int k = j >> 7, i = j & 127;
        v = w2[k * 16384 + i * 128 + o];
    } else {
        int i = j - 16384;
        v = b2[i * 128 + o];
    }
    __nv_bfloat16 hi = __float2bfloat16(v);
    float lo = v - __bfloat162float(hi);
    d_Bh[idx] = hi;
    d_Bl[idx] = __float2bfloat16(lo);
}

// ---------------- layer-1 scatter (fp32, in_c = 3) ----------------
__global__ void k_scatter3(const float* __restrict__ X, const int* __restrict__ ei) {
    constexpr int INC = 3;
    constexpr int KI = 128 * INC;          // 384
    constexpr int KIext = KI + INC;        // 387
    constexpr int KP = 392;
    __shared__ float sh_h[32 * 128];
    __shared__ float sh_x[32 * INC];
    __shared__ int sh_e[32];

    int n = blockIdx.x;
    int deg = d_cnt[n];
    int off = d_off[n];
    int tid = threadIdx.x;

    int base = 0;
    while (true) {
        int c = deg - base; if (c > 32) c = 32; if (c < 0) c = 0;
        if (tid < c) sh_e[tid] = d_eperm[off + base + tid];
        __syncthreads();
        for (int t = tid; t < c * 128; t += 256) {
            int dd = t >> 7, k = t & 127;
            sh_h[dd * 128 + k] = d_Hc[sh_e[dd] * HDIM + k];
        }
        for (int t = tid; t < c * INC; t += 256) {
            int dd = t / INC, i = t - dd * INC;
            int s = ei[sh_e[dd]];
            sh_x[dd * INC + i] = X[s * INC + i];
        }
        __syncthreads();
        for (int j = tid; j < KP; j += 256) {
            float v = 0.f;
            if (j < KI) {
                int k = j / INC, i = j - k * INC;
                for (int dd = 0; dd < c; dd++)
                    v += sh_h[dd * 128 + k] * sh_x[dd * INC + i];
            } else if (j < KIext) {
                int i = j - KI;
                for (int dd = 0; dd < c; dd++)
                    v += sh_x[dd * INC + i];
            }
            size_t idx = (size_t)n * KP + j;
            if (base == 0) d_M[idx] = v;
            else           d_M[idx] += v;
        }
        __syncthreads();
        base += 32;
        if (base >= deg) break;
    }
}

// ---------------- layer-2/3 scatter -> bf16 hi/lo split ----------------
__global__ void k_scatter_bf16(const float* __restrict__ X, const int* __restrict__ ei) {
    constexpr int KI = 16384;
    __shared__ float sh_h[32 * 128];
    __shared__ float sh_x[32 * 128];
    __shared__ int sh_e[32];

    int n = blockIdx.x;
    int deg = d_cnt[n];
    int off = d_off[n];
    int tid = threadIdx.x;

    int base = 0;
    while (true) {
        int c = deg - base; if (c > 32) c = 32; if (c < 0) c = 0;
        if (tid < c) sh_e[tid] = d_eperm[off + base + tid];
        __syncthreads();
        for (int t = tid; t < c * 128; t += 256) {
            int dd = t >> 7, k = t & 127;
            sh_h[dd * 128 + k] = d_Hc[sh_e[dd] * HDIM + k];
            int s = ei[sh_e[dd]];
            sh_x[dd * 128 + k] = X[s * 128 + k];
        }
        __syncthreads();
        for (int j = tid; j < KP23; j += 256) {
            float v = 0.f;
            if (j < KI) {
                int k = j >> 7, i = j & 127;
                for (int dd = 0; dd < c; dd++)
                    v += sh_h[dd * 128 + k] * sh_x[dd * 128 + i];
            } else {
                int i = j - KI;
                for (int dd = 0; dd < c; dd++)
                    v += sh_x[dd * 128 + i];
            }
            size_t idx = (size_t)n * KP23 + j;
            if (base != 0)
                v += __bfloat162float(d_Ah[idx]) + __bfloat162float(d_Al[idx]);
            __nv_bfloat16 hi = __float2bfloat16(v);
            float lo = v - __bfloat162float(hi);
            d_Ah[idx] = hi;
            d_Al[idx] = __float2bfloat16(lo);
        }
        __syncthreads();
        base += 32;
        if (base >= deg) break;
    }
}

// ---------------- zero AGG ----------------
__global__ void k_zero_agg() {
    int i = blockIdx.x * blockDim.x + threadIdx.x;
    if (i < N_NODES * HDIM) d_AGG[i] = 0.f;
}

// ---------------- layer-1 fp32 GEMM (small K) ----------------
__global__ __launch_bounds__(256) void k_gemm(int K, int chunk) {
    __shared__ float As[8 * 128];
    __shared__ float Bs[8 * 128];
    int row0 = blockIdx.x * 128;
    int kb = blockIdx.y * chunk;
    int ke = kb + chunk; if (ke > K) ke = K;
    int tid = threadIdx.x;
    int tr = tid >> 4, tc = tid & 15;
    float acc[8][8];
#pragma unroll
    for (int m = 0; m < 8; m++)
#pragma unroll
        for (int n = 0; n < 8; n++) acc[m][n] = 0.f;

    int ar = tid >> 1, ac = (tid & 1) * 4;
    int br = tid >> 5, bc = (tid & 31) * 4;

    for (int k0 = kb; k0 < ke; k0 += 8) {
        float4 av = *(const float4*)&d_M[(size_t)(row0 + ar) * K + k0 + ac];
        float4 bv = *(const float4*)&d_W2p[(k0 + br) * HDIM + bc];
        As[(ac + 0) * 128 + ar] = av.x;
        As[(ac + 1) * 128 + ar] = av.y;
        As[(ac + 2) * 128 + ar] = av.z;
        As[(ac + 3) * 128 + ar] = av.w;
        *(float4*)&Bs[br * 128 + bc] = bv;
        __syncthreads();
#pragma unroll
        for (int kk = 0; kk < 8; kk++) {
            float a[8], b[8];
#pragma unroll
            for (int m = 0; m < 8; m++) a[m] = As[kk * 128 + tr * 8 + m];
#pragma unroll
            for (int n = 0; n < 8; n++) b[n] = Bs[kk * 128 + tc * 8 + n];
#pragma unroll
            for (int m = 0; m < 8; m++)
#pragma unroll
                for (int n = 0; n < 8; n++)
                    acc[m][n] += a[m] * b[n];
        }
        __syncthreads();
    }
#pragma unroll
    for (int m = 0; m < 8; m++) {
        int r = row0 + tr * 8 + m;
#pragma unroll
        for (int n = 0; n < 8; n++)
            atomicAdd(&d_AGG[r * HDIM + tc * 8 + n], acc[m][n]);
    }
}

// ---------------- HMMA GEMM: AGG += A @ B^T, 3-pass bf16 hi/lo split ----------------
// grid (32 row-tiles, KSPLIT), 256 threads (8 warps). K-chunk = 64 bf16 (128 B/row).
// Stage = {Ah, Al, Bh, Bl} tiles of 16 KB = 64 KB; double-buffered in dynamic smem.
// Warp tile 32m x 64n via m16n8k16; fp32 accum in registers; atomicAdd epilogue.
__global__ __launch_bounds__(256, 1) void k_gemm_mma() {
    extern __shared__ char dynraw[];
    uint32_t tiles = (smem_u32(dynraw) + 1023) & ~1023u;

    int tid = threadIdx.x;
    int wid = tid >> 5, lane = tid & 31;
    int row0 = blockIdx.x * 128;
    int kz = blockIdx.y;
    int wm = (wid & 3) * 32;       // warp m-offset within 128
    int wn = (wid >> 2) * 64;      // warp n-offset within 128

    int c0 = (kz * NCHUNK) / KSPLIT;
    int c1 = ((kz + 1) * NCHUNK) / KSPLIT;
    int ncl = c1 - c0;

    int lrow = tid >> 1;           // 128 rows, 2 threads per row
    int lq = (tid & 1) * 4;        // each thread: 4 x 16B = 64 B of the 128 B row
    const char* gAh = (const char*)(d_Ah + (size_t)(row0 + lrow) * KP23);
    const char* gAl = (const char*)(d_Al + (size_t)(row0 + lrow) * KP23);
    const char* gBh = (const char*)(d_Bh + (size_t)lrow * KP23);
    const char* gBl = (const char*)(d_Bl + (size_t)lrow * KP23);

    float acc[2][8][4];
#pragma unroll
    for (int mt = 0; mt < 2; mt++)
#pragma unroll
        for (int n8 = 0; n8 < 8; n8++)
#pragma unroll
            for (int q = 0; q < 4; q++) acc[mt][n8][q] = 0.f;

    // precomputed swizzled smem offsets (base row offsets; swizzle commutes with +16B within row)
    uint32_t st_off[4];
#pragma unroll
    for (int q = 0; q < 4; q++)
        st_off[q] = SW128((uint32_t)(lrow * 128 + (lq + q) * 16));

    auto load_stage = [&](int cc, int s) {
        uint32_t sb = tiles + s * 65536;
        int kb = (c0 + cc) * 128;                       // byte offset along K
        const char* srcs[4] = { gAh + kb, gAl + kb, gBh + kb, gBl + kb };
#pragma unroll
        for (int t = 0; t < 4; t++) {
            uint32_t tb = sb + t * 16384;
#pragma unroll
            for (int q = 0; q < 4; q++)
                cpa16(tb + st_off[q], srcs[t] + (lq + q) * 16);
        }
    };

    load_stage(0, 0); CPA_COMMIT();

    for (int cc = 0; cc < ncl; cc++) {
        int s = cc & 1;
        if (cc + 1 < ncl) {
            load_stage(cc + 1, s ^ 1); CPA_COMMIT();
            CPA_WAIT1();
        } else {
            CPA_WAIT0();
        }
        __syncthreads();

        uint32_t sb = tiles + s * 65536;
#pragma unroll
        for (int kk = 0; kk < 4; kk++) {
            uint32_t ah[2][4], al[2][4], bh[4][4], bl[4][4];
#pragma unroll
            for (int mt = 0; mt < 2; mt++) {
                // lanes 0-15 -> rows 0..15 (k lo 16B), lanes 16-31 -> rows 0..15 (k hi 16B)
                uint32_t off = (uint32_t)((wm + mt * 16 + (lane & 15)) * 128
                                          + kk * 32 + (lane >> 4) * 16);
                uint32_t sw = SW128(off);
                ldsm_x4(ah[mt], sb + sw);
                ldsm_x4(al[mt], sb + 16384 + sw);
            }
#pragma unroll
            for (int nt = 0; nt < 4; nt++) {
                // M0: n-lo k-lo, M1: n-lo k-hi, M2: n-hi k-lo, M3: n-hi k-hi
                uint32_t off = (uint32_t)((wn + nt * 16 + (lane & 7) + ((lane >> 4) & 1) * 8) * 128
                                          + kk * 32 + ((lane >> 3) & 1) * 16);
                uint32_t sw = SW128(off);
                ldsm_x4(bh[nt], sb + 32768 + sw);
                ldsm_x4(bl[nt], sb + 49152 + sw);
            }
#pragma unroll
            for (int mt = 0; mt < 2; mt++)
#pragma unroll
                for (int n8 = 0; n8 < 8; n8++) {
                    int nt = n8 >> 1, h = (n8 & 1) * 2;
                    mma_bf16(acc[mt][n8], ah[mt], bh[nt][h], bh[nt][h + 1]);
                    mma_bf16(acc[mt][n8], al[mt], bh[nt][h], bh[nt][h + 1]);
                    mma_bf16(acc[mt][n8], ah[mt], bl[nt][h], bl[nt][h + 1]);
                }
        }
        __syncthreads();
    }

    // epilogue: split-K reduction via atomics
#pragma unroll
    for (int mt = 0; mt < 2; mt++) {
        int r = row0 + wm + mt * 16 + (lane >> 2);
#pragma unroll
        for (int n8 = 0; n8 < 8; n8++) {
            int cb = wn + n8 * 8 + (lane & 3) * 2;
            atomicAdd(&d_AGG[r * HDIM + cb],           acc[mt][n8][0]);
            atomicAdd(&d_AGG[r * HDIM + cb + 1],       acc[mt][n8][1]);
            atomicAdd(&d_AGG[(r + 8) * HDIM + cb],     acc[mt][n8][2]);
            atomicAdd(&d_AGG[(r + 8) * HDIM + cb + 1], acc[mt][n8][3]);
        }
    }
}

// ---------------- combine: agg/cnt + x@root + bias -> LN -> activation ----------------
template <int INC, int ACT>
__global__ void k_combine(const float* __restrict__ Xin,
                          const float* __restrict__ root,
                          const float* __restrict__ bias,
                          const float* __restrict__ lng,
                          const float* __restrict__ lnb,
                          float* __restrict__ Xout) {
    __shared__ float shx[INC];
    __shared__ float red[4];
    int n = blockIdx.x;
    int o = threadIdx.x;
    for (int i = o; i < INC; i += 128) shx[i] = Xin[n * INC + i];
    __syncthreads();

    float r = bias[o];
#pragma unroll 4
    for (int i = 0; i < INC; i++) r += shx[i] * root[i * HDIM + o];

    float cnt = (float)max(d_cnt[n], 1);
    float pre = d_AGG[n * HDIM + o] / cnt + r;

    float v = pre;
    for (int s = 16; s; s >>= 1) v += __shfl_xor_sync(0xffffffffu, v, s);
    if ((o & 31) == 0) red[o >> 5] = v;
    __syncthreads();
    float mean = (red[0] + red[1] + red[2] + red[3]) * (1.f / 128.f);
    __syncthreads();

    float cen = pre - mean;
    float v2 = cen * cen;
    for (int s = 16; s; s >>= 1) v2 += __shfl_xor_sync(0xffffffffu, v2, s);
    if ((o & 31) == 0) red[o >> 5] = v2;
    __syncthreads();
    float var = (red[0] + red[1] + red[2] + red[3]) * (1.f / 128.f);

    float y = cen * rsqrtf(var + LN_EPS) * lng[o] + lnb[o];
    if (ACT == 0)      y = fmaxf(y, 0.f);
    else if (ACT == 1) y = (y > 0.f) ? y : expm1f(y);
    else               y = (y >= 0.f) ? y : 0.01f * y;
    Xout[n * HDIM + o] = y;
}

// ---------------- pool (mean + max per graph) + final linear ----------------
__global__ void k_pool(const float* __restrict__ X,
                       const float* __restrict__ ct,
                       const float* __restrict__ ls,
                       const float* __restrict__ lw,
                       const float* __restrict__ lb,
                       float* __restrict__ out) {
    __shared__ float cat[261];
    int g = blockIdx.x;
    int o = threadIdx.x;
    int start = 0;
    for (int q = 0; q < g; q++) start += d_gcnt[q];
    int c = d_gcnt[g];
    float s = 0.f, mx = -INFINITY;
    for (int t = 0; t < c; t++) {
        float v = X[(size_t)(start + t) * HDIM + o];
        s += v;
        mx = fmaxf(mx, v);
    }
    cat[o]       = s / fmaxf((float)c, 1.f);
    cat[128 + o] = (c > 0) ? mx : 0.f;
    if (o < 4)  cat[256 + o] = ct[g * 4 + o];
    if (o == 4) cat[260] = ls[g];
    __syncthreads();
    if (o < 2) {
        float acc = lb[o];
        for (int j = 0; j < 261; j++) acc += cat[j] * lw[j * 2 + o];
        out[g * 2 + o] = acc;
    }
}

// ---------------- launch ----------------
extern "C" void kernel_launch(void* const* d_in, const int* in_sizes, int n_in,
                              void* d_out, int out_size) {
    const float* x     = (const float*)d_in[0];
    const int*   ei    = (const int*)  d_in[1];
    const float* ea    = (const float*)d_in[2];
    const int*   batch = (const int*)  d_in[3];
    const float* ct    = (const float*)d_in[4];
    const float* ls    = (const float*)d_in[5];

    const float* w1[3]   = {(const float*)d_in[6],  (const float*)d_in[12], (const float*)d_in[18]};
    const float* b1[3]   = {(const float*)d_in[7],  (const float*)d_in[13], (const float*)d_in[19]};
    const float* w2[3]   = {(const float*)d_in[8],  (const float*)d_in[14], (const float*)d_in[20]};
    const float* b2[3]   = {(const float*)d_in[9],  (const float*)d_in[15], (const float*)d_in[21]};
    const float* root[3] = {(const float*)d_in[10], (const float*)d_in[16], (const float*)d_in[22]};
    const float* bias[3] = {(const float*)d_in[11], (const float*)d_in[17], (const float*)d_in[23]};

    const float* lng[3] = {(const float*)d_in[24], (const float*)d_in[26], (const float*)d_in[28]};
    const float* lnb[3] = {(const float*)d_in[25], (const float*)d_in[27], (const float*)d_in[29]};
    const float* lw = (const float*)d_in[30];
    const float* lb = (const float*)d_in[31];
    float* out = (float*)d_out;

    float *pXA, *pXB;
    cudaGetSymbolAddress((void**)&pXA, d_XA);
    cudaGetSymbolAddress((void**)&pXB, d_XB);

    const int GEMM_SMEM = 2 * 65536 + 1024;
    cudaFuncSetAttribute(k_gemm_mma, cudaFuncAttributeMaxDynamicSharedMemorySize, GEMM_SMEM);

    // CSR by dst + graph histogram (reused by all layers)
    k_zero_counters<<<16, 256>>>();
    k_hist<<<64, 256>>>(ei, batch);
    k_scan<<<1, 1024>>>();
    k_fill<<<64, 256>>>(ei);

    // ---- layer 1 (in_c = 3, relu) — fp32 SIMT path, tiny K ----
    k_edge_mlp<<<N_EDGES, 128>>>(ea, w1[0], b1[0]);
    k_permw2<<<(KP_L1 * HDIM + 255) / 256, 256>>>(w2[0], b2[0], 3, KP_L1);
    k_scatter3<<<N_NODES, 256>>>(x, ei);
    k_zero_agg<<<512, 1024>>>();
    k_gemm<<<dim3(32, 7), 256>>>(KP_L1, 56);
    k_combine<3, 0><<<N_NODES, 128>>>(x, root[0], bias[0], lng[0], lnb[0], pXA);

    // ---- layer 2 (in_c = 128, elu) — HMMA path ----
    k_edge_mlp<<<N_EDGES, 128>>>(ea, w1[1], b1[1]);
    k_permw2_bf16<<<(HDIM * KP23 + 255) / 256, 256>>>(w2[1], b2[1]);
    k_scatter_bf16<<<N_NODES, 256>>>(pXA, ei);
    k_zero_agg<<<512, 1024>>>();
    k_gemm_mma<<<dim3(32, KSPLIT), 256, GEMM_SMEM>>>();
    k_combine<128, 1><<<N_NODES, 128>>>(pXA, root[1], bias[1], lng[1], lnb[1], pXB);

    // ---- layer 3 (in_c = 128, leaky_relu) — HMMA path ----
    k_edge_mlp<<<N_EDGES, 128>>>(ea, w1[2], b1[2]);
    k_permw2_bf16<<<(HDIM * KP23 + 255) / 256, 256>>>(w2[2], b2[2]);
    k_scatter_bf16<<<N_NODES, 256>>>(pXB, ei);
    k_zero_agg<<<512, 1024>>>();
    k_gemm_mma<<<dim3(32, KSPLIT), 256, GEMM_SMEM>>>();
    k_combine<128, 2><<<N_NODES, 128>>>(pXB, root[2], bias[2], lng[2], lnb[2], pXA);

    // ---- pooling + final linear ----
    k_pool<<<N_GRAPHS, 128>>>(pXA, ct, ls, lw, lb, out);
}

// round 4
// speedup vs baseline: 1.9341x; 1.1146x over previous
#include <cuda_runtime.h>
#include <cuda_bf16.h>
#include <math.h>
#include <stdint.h>

#define N_NODES 4096
#define N_EDGES 16384
#define N_GRAPHS 16
#define HDIM 128
#define LN_EPS 1e-5f

// layer1: KI=128*3=384, +3 bias rows = 387 -> pad 392 (fp32 SIMT path, tiny)
// layer2/3: KI=128*128=16384, +128 bias rows = 16512 (HMMA path)
static const int KP_L1 = 392;
#define KP23 16512
#define NCHUNK 258          // 16512 / 64
#define KSPLIT 4
#define NGROUPS 2064        // 16512 / 8

// ---------------- device scratch (no allocations allowed) ----------------
__device__ float d_M[(size_t)N_NODES * KP_L1];           // layer-1 fp32 M
__device__ float d_W2p[KP_L1 * HDIM];                    // layer-1 permuted w2
__device__ __nv_bfloat16 d_Ah[(size_t)N_NODES * KP23];   // hi(M) bf16
__device__ __nv_bfloat16 d_Al[(size_t)N_NODES * KP23];   // lo(M) bf16
__device__ __nv_bfloat16 d_Bh[(size_t)HDIM * KP23];      // hi(W2p^T) [o, j]
__device__ __nv_bfloat16 d_Bl[(size_t)HDIM * KP23];      // lo(W2p^T)
__device__ float d_Hc[N_EDGES * HDIM];
__device__ float d_XA[N_NODES * HDIM];
__device__ float d_XB[N_NODES * HDIM];
__device__ float d_AGG[N_NODES * HDIM];
__device__ int d_cnt[N_NODES];
__device__ int d_off[N_NODES];
__device__ int d_cur[N_NODES];
__device__ int d_eperm[N_EDGES];
__device__ int d_gcnt[N_GRAPHS];

// ---------------- PTX helpers (baseline ISA only — no sm_103a-only ops) ----------------
__device__ __forceinline__ uint32_t smem_u32(const void* p) {
    uint32_t a;
    asm("{ .reg .u64 t; cvta.to.shared.u64 t, %1; cvt.u32.u64 %0, t; }" : "=r"(a) : "l"(p));
    return a;
}
__device__ __forceinline__ void cpa16(uint32_t smem_addr, const void* g) {
    asm volatile("cp.async.cg.shared.global [%0], [%1], 16;" :: "r"(smem_addr), "l"(g));
}
#define CPA_COMMIT() asm volatile("cp.async.commit_group;" ::: "memory")
#define CPA_WAIT0()  asm volatile("cp.async.wait_group 0;" ::: "memory")
#define CPA_WAIT1()  asm volatile("cp.async.wait_group 1;" ::: "memory")

__device__ __forceinline__ void ldsm_x4(uint32_t* r, uint32_t addr) {
    asm volatile("ldmatrix.sync.aligned.m8n8.x4.shared.b16 {%0,%1,%2,%3}, [%4];"
                 : "=r"(r[0]), "=r"(r[1]), "=r"(r[2]), "=r"(r[3]) : "r"(addr));
}
__device__ __forceinline__ void mma_bf16(float* c, const uint32_t* a, uint32_t b0, uint32_t b1) {
    asm volatile("mma.sync.aligned.m16n8k16.row.col.f32.bf16.bf16.f32 "
                 "{%0,%1,%2,%3}, {%4,%5,%6,%7}, {%8,%9}, {%0,%1,%2,%3};"
                 : "+f"(c[0]), "+f"(c[1]), "+f"(c[2]), "+f"(c[3])
                 : "r"(a[0]), "r"(a[1]), "r"(a[2]), "r"(a[3]), "r"(b0), "r"(b1));
}
#define SW128(off) ((off) ^ (((off) >> 3) & 0x70))

// ---------------- CSR build ----------------
__global__ void k_zero_counters() {
    int i = blockIdx.x * blockDim.x + threadIdx.x;
    if (i < N_NODES) { d_cnt[i] = 0; d_cur[i] = 0; }
    if (i < N_GRAPHS) d_gcnt[i] = 0;
}

__global__ void k_hist(const int* __restrict__ ei, const int* __restrict__ batch) {
    int e = blockIdx.x * blockDim.x + threadIdx.x;
    if (e < N_EDGES) atomicAdd(&d_cnt[ei[N_EDGES + e]], 1);
    if (e < N_NODES) atomicAdd(&d_gcnt[batch[e]], 1);
}

__global__ void k_scan() {
    __shared__ int part[1024];
    int t = threadIdx.x;
    int v0 = d_cnt[t*4], v1 = d_cnt[t*4+1], v2 = d_cnt[t*4+2], v3 = d_cnt[t*4+3];
    int s = v0 + v1 + v2 + v3;
    part[t] = s;
    __syncthreads();
    for (int d = 1; d < 1024; d <<= 1) {
        int add = (t >= d) ? part[t - d] : 0;
        __syncthreads();
        part[t] += add;
        __syncthreads();
    }
    int excl = part[t] - s;
    d_off[t*4]   = excl;
    d_off[t*4+1] = excl + v0;
    d_off[t*4+2] = excl + v0 + v1;
    d_off[t*4+3] = excl + v0 + v1 + v2;
}

__global__ void k_fill(const int* __restrict__ ei) {
    int e = blockIdx.x * blockDim.x + threadIdx.x;
    if (e < N_EDGES) {
        int d = ei[N_EDGES + e];
        int p = atomicAdd(&d_cur[d], 1);
        d_eperm[d_off[d] + p] = e;
    }
}

// ---------------- edge MLP: h = relu(ea @ w1 + b1) ----------------
__global__ void k_edge_mlp(const float* __restrict__ ea,
                           const float* __restrict__ w1,
                           const float* __restrict__ b1) {
    int e = blockIdx.x;
    int o = threadIdx.x;
    float4 a = *(const float4*)&ea[e * 4];
    float v = b1[o] + a.x * w1[o] + a.y * w1[128 + o] + a.z * w1[256 + o] + a.w * w1[384 + o];
    d_Hc[e * HDIM + o] = fmaxf(v, 0.f);
}

// ---------------- layer-1 permuted w2 (fp32) ----------------
__global__ void k_permw2(const float* __restrict__ w2, const float* __restrict__ b2,
                         int in_c, int KP) {
    int idx = blockIdx.x * blockDim.x + threadIdx.x;
    if (idx >= KP * HDIM) return;
    int j = idx >> 7, o = idx & 127;
    int KI = 128 * in_c;
    float v = 0.f;
    if (j < KI) {
        int k = j / in_c, i = j - k * in_c;
        v = w2[k * (in_c * HDIM) + i * HDIM + o];
    } else if (j < KI + in_c) {
        int i = j - KI;
        v = b2[i * HDIM + o];
    }
    d_W2p[idx] = v;
}

// ---------------- layer-2/3 B matrix: [o, j] bf16 hi/lo, 8-wide packed stores ----------------
// grid (NGROUPS/256 -> 9, 128), block 256: o = blockIdx.y, g = group index
__global__ void k_permw2_bf16(const float* __restrict__ w2, const float* __restrict__ b2) {
    int g = blockIdx.x * blockDim.x + threadIdx.x;
    if (g >= NGROUPS) return;
    int o = blockIdx.y;
    int j0 = g * 8;
    float v[8];
    if (j0 < 16384) {
        int k = j0 >> 7, i0 = j0 & 127;
#pragma unroll
        for (int q = 0; q < 8; q++)
            v[q] = w2[k * 16384 + (i0 + q) * 128 + o];
    } else {
        int i0 = j0 - 16384;
#pragma unroll
        for (int q = 0; q < 8; q++)
            v[q] = b2[(i0 + q) * 128 + o];
    }
    __nv_bfloat162 hh[4], ll[4];
#pragma unroll
    for (int q = 0; q < 4; q++) {
        __nv_bfloat16 a = __float2bfloat16(v[2*q]);
        __nv_bfloat16 b = __float2bfloat16(v[2*q+1]);
        hh[q] = __nv_bfloat162(a, b);
        ll[q] = __nv_bfloat162(__float2bfloat16(v[2*q]   - __bfloat162float(a)),
                               __float2bfloat16(v[2*q+1] - __bfloat162float(b)));
    }
    size_t idx = (size_t)o * KP23 + j0;
    *(uint4*)&d_Bh[idx] = *(uint4*)hh;
    *(uint4*)&d_Bl[idx] = *(uint4*)ll;
}

// ---------------- layer-1 scatter (fp32, in_c = 3) ----------------
__global__ void k_scatter3(const float* __restrict__ X, const int* __restrict__ ei) {
    constexpr int INC = 3;
    constexpr int KI = 128 * INC;          // 384
    constexpr int KIext = KI + INC;        // 387
    constexpr int KP = 392;
    __shared__ float sh_h[32 * 128];
    __shared__ float sh_x[32 * INC];
    __shared__ int sh_e[32];

    int n = blockIdx.x;
    int deg = d_cnt[n];
    int off = d_off[n];
    int tid = threadIdx.x;

    int base = 0;
    while (true) {
        int c = deg - base; if (c > 32) c = 32; if (c < 0) c = 0;
        if (tid < c) sh_e[tid] = d_eperm[off + base + tid];
        __syncthreads();
        for (int t = tid; t < c * 128; t += 256) {
            int dd = t >> 7, k = t & 127;
            sh_h[dd * 128 + k] = d_Hc[sh_e[dd] * HDIM + k];
        }
        for (int t = tid; t < c * INC; t += 256) {
            int dd = t / INC, i = t - dd * INC;
            int s = ei[sh_e[dd]];
            sh_x[dd * INC + i] = X[s * INC + i];
        }
        __syncthreads();
        for (int j = tid; j < KP; j += 256) {
            float v = 0.f;
            if (j < KI) {
                int k = j / INC, i = j - k * INC;
                for (int dd = 0; dd < c; dd++)
                    v += sh_h[dd * 128 + k] * sh_x[dd * INC + i];
            } else if (j < KIext) {
                int i = j - KI;
                for (int dd = 0; dd < c; dd++)
                    v += sh_x[dd * INC + i];
            }
            size_t idx = (size_t)n * KP + j;
            if (base == 0) d_M[idx] = v;
            else           d_M[idx] += v;
        }
        __syncthreads();
        base += 32;
        if (base >= deg) break;
    }
}

// ---------------- layer-2/3 scatter -> bf16 hi/lo, 8-wide j groups + packed stores ----------------
__global__ __launch_bounds__(256) void k_scatter_bf16(const float* __restrict__ X,
                                                      const int* __restrict__ ei) {
    __shared__ float sh_h[32 * 128];
    __shared__ float sh_x[32 * 128];
    __shared__ int sh_e[32];

    int n = blockIdx.x;
    int deg = d_cnt[n];
    int off = d_off[n];
    int tid = threadIdx.x;

    int base = 0;
    while (true) {
        int c = deg - base; if (c > 32) c = 32; if (c < 0) c = 0;
        if (tid < c) sh_e[tid] = d_eperm[off + base + tid];
        __syncthreads();
        for (int t = tid; t < c * 128; t += 256) {
            int dd = t >> 7, k = t & 127;
            sh_h[dd * 128 + k] = d_Hc[sh_e[dd] * HDIM + k];
            int s = ei[sh_e[dd]];
            sh_x[dd * 128 + k] = X[s * 128 + k];
        }
        __syncthreads();

        // 8-wide j groups: k constant within group, i0..i0+7 consecutive
        for (int g = tid; g < NGROUPS; g += 256) {
            int j0 = g * 8;
            float v[8];
#pragma unroll
            for (int q = 0; q < 8; q++) v[q] = 0.f;

            if (j0 < 16384) {
                int k = j0 >> 7, i0 = j0 & 127;
                for (int dd = 0; dd < c; dd++) {
                    float h = sh_h[dd * 128 + k];
                    float4 xa = *(const float4*)&sh_x[dd * 128 + i0];
                    float4 xb = *(const float4*)&sh_x[dd * 128 + i0 + 4];
                    v[0] += h * xa.x; v[1] += h * xa.y; v[2] += h * xa.z; v[3] += h * xa.w;
                    v[4] += h * xb.x; v[5] += h * xb.y; v[6] += h * xb.z; v[7] += h * xb.w;
                }
            } else {
                int i0 = j0 - 16384;
                for (int dd = 0; dd < c; dd++) {
                    float4 xa = *(const float4*)&sh_x[dd * 128 + i0];
                    float4 xb = *(const float4*)&sh_x[dd * 128 + i0 + 4];
                    v[0] += xa.x; v[1] += xa.y; v[2] += xa.z; v[3] += xa.w;
                    v[4] += xb.x; v[5] += xb.y; v[6] += xb.z; v[7] += xb.w;
                }
            }

            size_t idx = (size_t)n * KP23 + j0;
            if (base != 0) {   // rare multi-pass: accumulate previous stored value
                uint4 ph = *(const uint4*)&d_Ah[idx];
                uint4 pl = *(const uint4*)&d_Al[idx];
                const __nv_bfloat162* hp = (const __nv_bfloat162*)&ph;
                const __nv_bfloat162* lp = (const __nv_bfloat162*)&pl;
#pragma unroll
                for (int q = 0; q < 4; q++) {
                    v[2*q]   += __low2float(hp[q])  + __low2float(lp[q]);
                    v[2*q+1] += __high2float(hp[q]) + __high2float(lp[q]);
                }
            }

            __nv_bfloat162 hh[4], ll[4];
#pragma unroll
            for (int q = 0; q < 4; q++) {
                __nv_bfloat16 a = __float2bfloat16(v[2*q]);
                __nv_bfloat16 b = __float2bfloat16(v[2*q+1]);
                hh[q] = __nv_bfloat162(a, b);
                ll[q] = __nv_bfloat162(__float2bfloat16(v[2*q]   - __bfloat162float(a)),
                                       __float2bfloat16(v[2*q+1] - __bfloat162float(b)));
            }
            *(uint4*)&d_Ah[idx] = *(uint4*)hh;
            *(uint4*)&d_Al[idx] = *(uint4*)ll;
        }
        __syncthreads();
        base += 32;
        if (base >= deg) break;
    }
}

// ---------------- zero AGG ----------------
__global__ void k_zero_agg() {
    int i = blockIdx.x * blockDim.x + threadIdx.x;
    if (i < N_NODES * HDIM) d_AGG[i] = 0.f;
}

// ---------------- layer-1 fp32 GEMM (small K) ----------------
__global__ __launch_bounds__(256) void k_gemm(int K, int chunk) {
    __shared__ float As[8 * 128];
    __shared__ float Bs[8 * 128];
    int row0 = blockIdx.x * 128;
    int kb = blockIdx.y * chunk;
    int ke = kb + chunk; if (ke > K) ke = K;
    int tid = threadIdx.x;
    int tr = tid >> 4, tc = tid & 15;
    float acc[8][8];
#pragma unroll
    for (int m = 0; m < 8; m++)
#pragma unroll
        for (int n = 0; n < 8; n++) acc[m][n] = 0.f;

    int ar = tid >> 1, ac = (tid & 1) * 4;
    int br = tid >> 5, bc = (tid & 31) * 4;

    for (int k0 = kb; k0 < ke; k0 += 8) {
        float4 av = *(const float4*)&d_M[(size_t)(row0 + ar) * K + k0 + ac];
        float4 bv = *(const float4*)&d_W2p[(k0 + br) * HDIM + bc];
        As[(ac + 0) * 128 + ar] = av.x;
        As[(ac + 1) * 128 + ar] = av.y;
        As[(ac + 2) * 128 + ar] = av.z;
        As[(ac + 3) * 128 + ar] = av.w;
        *(float4*)&Bs[br * 128 + bc] = bv;
        __syncthreads();
#pragma unroll
        for (int kk = 0; kk < 8; kk++) {
            float a[8], b[8];
#pragma unroll
            for (int m = 0; m < 8; m++) a[m] = As[kk * 128 + tr * 8 + m];
#pragma unroll
            for (int n = 0; n < 8; n++) b[n] = Bs[kk * 128 + tc * 8 + n];
#pragma unroll
            for (int m = 0; m < 8; m++)
#pragma unroll
                for (int n = 0; n < 8; n++)
                    acc[m][n] += a[m] * b[n];
        }
        __syncthreads();
    }
#pragma unroll
    for (int m = 0; m < 8; m++) {
        int r = row0 + tr * 8 + m;
#pragma unroll
        for (int n = 0; n < 8; n++)
            atomicAdd(&d_AGG[r * HDIM + tc * 8 + n], acc[m][n]);
    }
}

// ---------------- HMMA GEMM: AGG += A @ B^T, 3-pass bf16 hi/lo split ----------------
__global__ __launch_bounds__(256, 1) void k_gemm_mma() {
    extern __shared__ char dynraw[];
    uint32_t tiles = (smem_u32(dynraw) + 1023) & ~1023u;

    int tid = threadIdx.x;
    int wid = tid >> 5, lane = tid & 31;
    int row0 = blockIdx.x * 128;
    int kz = blockIdx.y;
    int wm = (wid & 3) * 32;       // warp m-offset within 128
    int wn = (wid >> 2) * 64;      // warp n-offset within 128

    int c0 = (kz * NCHUNK) / KSPLIT;
    int c1 = ((kz + 1) * NCHUNK) / KSPLIT;
    int ncl = c1 - c0;

    int lrow = tid >> 1;           // 128 rows, 2 threads per row
    int lq = (tid & 1) * 4;        // each thread: 4 x 16B = 64 B of the 128 B row
    const char* gAh = (const char*)(d_Ah + (size_t)(row0 + lrow) * KP23);
    const char* gAl = (const char*)(d_Al + (size_t)(row0 + lrow) * KP23);
    const char* gBh = (const char*)(d_Bh + (size_t)lrow * KP23);
    const char* gBl = (const char*)(d_Bl + (size_t)lrow * KP23);

    float acc[2][8][4];
#pragma unroll
    for (int mt = 0; mt < 2; mt++)
#pragma unroll
        for (int n8 = 0; n8 < 8; n8++)
#pragma unroll
            for (int q = 0; q < 4; q++) acc[mt][n8][q] = 0.f;

    uint32_t st_off[4];
#pragma unroll
    for (int q = 0; q < 4; q++)
        st_off[q] = SW128((uint32_t)(lrow * 128 + (lq + q) * 16));

    auto load_stage = [&](int cc, int s) {
        uint32_t sb = tiles + s * 65536;
        int kb = (c0 + cc) * 128;                       // byte offset along K
        const char* srcs[4] = { gAh + kb, gAl + kb, gBh + kb, gBl + kb };
#pragma unroll
        for (int t = 0; t < 4; t++) {
            uint32_t tb = sb + t * 16384;
#pragma unroll
            for (int q = 0; q < 4; q++)
                cpa16(tb + st_off[q], srcs[t] + (lq + q) * 16);
        }
    };

    load_stage(0, 0); CPA_COMMIT();

    for (int cc = 0; cc < ncl; cc++) {
        int s = cc & 1;
        if (cc + 1 < ncl) {
            load_stage(cc + 1, s ^ 1); CPA_COMMIT();
            CPA_WAIT1();
        } else {
            CPA_WAIT0();
        }
        __syncthreads();

        uint32_t sb = tiles + s * 65536;
#pragma unroll
        for (int kk = 0; kk < 4; kk++) {
            uint32_t ah[2][4], al[2][4], bh[4][4], bl[4][4];
#pragma unroll
            for (int mt = 0; mt < 2; mt++) {
                uint32_t off = (uint32_t)((wm + mt * 16 + (lane & 15)) * 128
                                          + kk * 32 + (lane >> 4) * 16);
                uint32_t sw = SW128(off);
                ldsm_x4(ah[mt], sb + sw);
                ldsm_x4(al[mt], sb + 16384 + sw);
            }
#pragma unroll
            for (int nt = 0; nt < 4; nt++) {
                uint32_t off = (uint32_t)((wn + nt * 16 + (lane & 7) + ((lane >> 4) & 1) * 8) * 128
                                          + kk * 32 + ((lane >> 3) & 1) * 16);
                uint32_t sw = SW128(off);
                ldsm_x4(bh[nt], sb + 32768 + sw);
                ldsm_x4(bl[nt], sb + 49152 + sw);
            }
#pragma unroll
            for (int mt = 0; mt < 2; mt++)
#pragma unroll
                for (int n8 = 0; n8 < 8; n8++) {
                    int nt = n8 >> 1, h = (n8 & 1) * 2;
                    mma_bf16(acc[mt][n8], ah[mt], bh[nt][h], bh[nt][h + 1]);
                    mma_bf16(acc[mt][n8], al[mt], bh[nt][h], bh[nt][h + 1]);
                    mma_bf16(acc[mt][n8], ah[mt], bl[nt][h], bl[nt][h + 1]);
                }
        }
        __syncthreads();
    }

    // epilogue: split-K reduction via atomics
#pragma unroll
    for (int mt = 0; mt < 2; mt++) {
        int r = row0 + wm + mt * 16 + (lane >> 2);
#pragma unroll
        for (int n8 = 0; n8 < 8; n8++) {
            int cb = wn + n8 * 8 + (lane & 3) * 2;
            atomicAdd(&d_AGG[r * HDIM + cb],           acc[mt][n8][0]);
            atomicAdd(&d_AGG[r * HDIM + cb + 1],       acc[mt][n8][1]);
            atomicAdd(&d_AGG[(r + 8) * HDIM + cb],     acc[mt][n8][2]);
            atomicAdd(&d_AGG[(r + 8) * HDIM + cb + 1], acc[mt][n8][3]);
        }
    }
}

// ---------------- combine: agg/cnt + x@root + bias -> LN -> activation ----------------
template <int INC, int ACT>
__global__ void k_combine(const float* __restrict__ Xin,
                          const float* __restrict__ root,
                          const float* __restrict__ bias,
                          const float* __restrict__ lng,
                          const float* __restrict__ lnb,
                          float* __restrict__ Xout) {
    __shared__ float shx[INC];
    __shared__ float red[4];
    int n = blockIdx.x;
    int o = threadIdx.x;
    for (int i = o; i < INC; i += 128) shx[i] = Xin[n * INC + i];
    __syncthreads();

    float r = bias[o];
#pragma unroll 4
    for (int i = 0; i < INC; i++) r += shx[i] * root[i * HDIM + o];

    float cnt = (float)max(d_cnt[n], 1);
    float pre = d_AGG[n * HDIM + o] / cnt + r;

    float v = pre;
    for (int s = 16; s; s >>= 1) v += __shfl_xor_sync(0xffffffffu, v, s);
    if ((o & 31) == 0) red[o >> 5] = v;
    __syncthreads();
    float mean = (red[0] + red[1] + red[2] + red[3]) * (1.f / 128.f);
    __syncthreads();

    float cen = pre - mean;
    float v2 = cen * cen;
    for (int s = 16; s; s >>= 1) v2 += __shfl_xor_sync(0xffffffffu, v2, s);
    if ((o & 31) == 0) red[o >> 5] = v2;
    __syncthreads();
    float var = (red[0] + red[1] + red[2] + red[3]) * (1.f / 128.f);

    float y = cen * rsqrtf(var + LN_EPS) * lng[o] + lnb[o];
    if (ACT == 0)      y = fmaxf(y, 0.f);
    else if (ACT == 1) y = (y > 0.f) ? y : expm1f(y);
    else               y = (y >= 0.f) ? y : 0.01f * y;
    Xout[n * HDIM + o] = y;
}

// ---------------- pool (mean + max per graph) + final linear ----------------
__global__ void k_pool(const float* __restrict__ X,
                       const float* __restrict__ ct,
                       const float* __restrict__ ls,
                       const float* __restrict__ lw,
                       const float* __restrict__ lb,
                       float* __restrict__ out) {
    __shared__ float cat[261];
    int g = blockIdx.x;
    int o = threadIdx.x;
    int start = 0;
    for (int q = 0; q < g; q++) start += d_gcnt[q];
    int c = d_gcnt[g];
    float s = 0.f, mx = -INFINITY;
    for (int t = 0; t < c; t++) {
        float v = X[(size_t)(start + t) * HDIM + o];
        s += v;
        mx = fmaxf(mx, v);
    }
    cat[o]       = s / fmaxf((float)c, 1.f);
    cat[128 + o] = (c > 0) ? mx : 0.f;
    if (o < 4)  cat[256 + o] = ct[g * 4 + o];
    if (o == 4) cat[260] = ls[g];
    __syncthreads();
    if (o < 2) {
        float acc = lb[o];
        for (int j = 0; j < 261; j++) acc += cat[j] * lw[j * 2 + o];
        out[g * 2 + o] = acc;
    }
}

// ---------------- launch ----------------
extern "C" void kernel_launch(void* const* d_in, const int* in_sizes, int n_in,
                              void* d_out, int out_size) {
    const float* x     = (const float*)d_in[0];
    const int*   ei    = (const int*)  d_in[1];
    const float* ea    = (const float*)d_in[2];
    const int*   batch = (const int*)  d_in[3];
    const float* ct    = (const float*)d_in[4];
    const float* ls    = (const float*)d_in[5];

    const float* w1[3]   = {(const float*)d_in[6],  (const float*)d_in[12], (const float*)d_in[18]};
    const float* b1[3]   = {(const float*)d_in[7],  (const float*)d_in[13], (const float*)d_in[19]};
    const float* w2[3]   = {(const float*)d_in[8],  (const float*)d_in[14], (const float*)d_in[20]};
    const float* b2[3]   = {(const float*)d_in[9],  (const float*)d_in[15], (const float*)d_in[21]};
    const float* root[3] = {(const float*)d_in[10], (const float*)d_in[16], (const float*)d_in[22]};
    const float* bias[3] = {(const float*)d_in[11], (const float*)d_in[17], (const float*)d_in[23]};

    const float* lng[3] = {(const float*)d_in[24], (const float*)d_in[26], (const float*)d_in[28]};
    const float* lnb[3] = {(const float*)d_in[25], (const float*)d_in[27], (const float*)d_in[29]};
    const float* lw = (const float*)d_in[30];
    const float* lb = (const float*)d_in[31];
    float* out = (float*)d_out;

    float *pXA, *pXB;
    cudaGetSymbolAddress((void**)&pXA, d_XA);
    cudaGetSymbolAddress((void**)&pXB, d_XB);

    const int GEMM_SMEM = 2 * 65536 + 1024;
    cudaFuncSetAttribute(k_gemm_mma, cudaFuncAttributeMaxDynamicSharedMemorySize, GEMM_SMEM);

    // CSR by dst + graph histogram (reused by all layers)
    k_zero_counters<<<16, 256>>>();
    k_hist<<<64, 256>>>(ei, batch);
    k_scan<<<1, 1024>>>();
    k_fill<<<64, 256>>>(ei);

    // ---- layer 1 (in_c = 3, relu) — fp32 SIMT path, tiny K ----
    k_edge_mlp<<<N_EDGES, 128>>>(ea, w1[0], b1[0]);
    k_permw2<<<(KP_L1 * HDIM + 255) / 256, 256>>>(w2[0], b2[0], 3, KP_L1);
    k_scatter3<<<N_NODES, 256>>>(x, ei);
    k_zero_agg<<<512, 1024>>>();
    k_gemm<<<dim3(32, 7), 256>>>(KP_L1, 56);
    k_combine<3, 0><<<N_NODES, 128>>>(x, root[0], bias[0], lng[0], lnb[0], pXA);

    // ---- layer 2 (in_c = 128, elu) — HMMA path ----
    k_edge_mlp<<<N_EDGES, 128>>>(ea, w1[1], b1[1]);
    k_permw2_bf16<<<dim3((NGROUPS + 255) / 256, 128), 256>>>(w2[1], b2[1]);
    k_scatter_bf16<<<N_NODES, 256>>>(pXA, ei);
    k_zero_agg<<<512, 1024>>>();
    k_gemm_mma<<<dim3(32, KSPLIT), 256, GEMM_SMEM>>>();
    k_combine<128, 1><<<N_NODES, 128>>>(pXA, root[1], bias[1], lng[1], lnb[1], pXB);

    // ---- layer 3 (in_c = 128, leaky_relu) — HMMA path ----
    k_edge_mlp<<<N_EDGES, 128>>>(ea, w1[2], b1[2]);
    k_permw2_bf16<<<dim3((NGROUPS + 255) / 256, 128), 256>>>(w2[2], b2[2]);
    k_scatter_bf16<<<N_NODES, 256>>>(pXB, ei);
    k_zero_agg<<<512, 1024>>>();
    k_gemm_mma<<<dim3(32, KSPLIT), 256, GEMM_SMEM>>>();
    k_combine<128, 2><<<N_NODES, 128>>>(pXB, root[2], bias[2], lng[2], lnb[2], pXA);

    // ---- pooling + final linear ----
    k_pool<<<N_GRAPHS, 128>>>(pXA, ct, ls, lw, lb, out);
}

// round 5
// speedup vs baseline: 2.2984x; 1.1883x over previous
#include <cuda_runtime.h>
#include <cuda_bf16.h>
#include <cuda_fp16.h>
#include <math.h>
#include <stdint.h>

#define N_NODES 4096
#define N_EDGES 16384
#define N_GRAPHS 16
#define HDIM 128
#define LN_EPS 1e-5f

// layer1: KI=384, +3 bias rows = 387 -> pad 392 (fp32 SIMT path)
// layer2/3: KI=16384, +128 bias rows = 16512 (HMMA fp16 2-pass path)
static const int KP_L1 = 392;
#define KP23 16512
#define NCHUNK 258          // 16512 / 64
#define KSPLIT 4
#define NGROUPS 2064        // 16512 / 8

// ---------------- device scratch ----------------
__device__ float d_M[(size_t)N_NODES * KP_L1];
__device__ float d_W2p[KP_L1 * HDIM];
__device__ __half d_Ah[(size_t)N_NODES * KP23];      // hi(M) fp16
__device__ __half d_Al[(size_t)N_NODES * KP23];      // lo(M) fp16
__device__ __half d_Bf2[(size_t)HDIM * KP23];        // fp16(W2p^T) layer 2
__device__ __half d_Bf3[(size_t)HDIM * KP23];        // fp16(W2p^T) layer 3
__device__ float d_Hc[(size_t)3 * N_EDGES * HDIM];   // edge MLP out, all layers
__device__ float d_XA[N_NODES * HDIM];
__device__ float d_XB[N_NODES * HDIM];
__device__ float d_AGG[N_NODES * HDIM];
__device__ int d_cnt[N_NODES];
__device__ int d_off[N_NODES];
__device__ int d_cur[N_NODES];
__device__ int d_eperm[N_EDGES];
__device__ int d_gcnt[N_GRAPHS];

// ---------------- PTX helpers (baseline ISA only) ----------------
__device__ __forceinline__ uint32_t smem_u32(const void* p) {
    uint32_t a;
    asm("{ .reg .u64 t; cvta.to.shared.u64 t, %1; cvt.u32.u64 %0, t; }" : "=r"(a) : "l"(p));
    return a;
}
__device__ __forceinline__ void cpa16(uint32_t smem_addr, const void* g) {
    asm volatile("cp.async.cg.shared.global [%0], [%1], 16;" :: "r"(smem_addr), "l"(g));
}
#define CPA_COMMIT() asm volatile("cp.async.commit_group;" ::: "memory")
#define CPA_WAIT0()  asm volatile("cp.async.wait_group 0;" ::: "memory")
#define CPA_WAIT1()  asm volatile("cp.async.wait_group 1;" ::: "memory")

__device__ __forceinline__ void ldsm_x4(uint32_t* r, uint32_t addr) {
    asm volatile("ldmatrix.sync.aligned.m8n8.x4.shared.b16 {%0,%1,%2,%3}, [%4];"
                 : "=r"(r[0]), "=r"(r[1]), "=r"(r[2]), "=r"(r[3]) : "r"(addr));
}
__device__ __forceinline__ void mma_f16(float* c, const uint32_t* a, uint32_t b0, uint32_t b1) {
    asm volatile("mma.sync.aligned.m16n8k16.row.col.f32.f16.f16.f32 "
                 "{%0,%1,%2,%3}, {%4,%5,%6,%7}, {%8,%9}, {%0,%1,%2,%3};"
                 : "+f"(c[0]), "+f"(c[1]), "+f"(c[2]), "+f"(c[3])
                 : "r"(a[0]), "r"(a[1]), "r"(a[2]), "r"(a[3]), "r"(b0), "r"(b1));
}
#define SW128(off) ((off) ^ (((off) >> 3) & 0x70))

// ---------------- init: zero AGG + counters (one launch) ----------------
__global__ void k_zero_all() {
    int i = blockIdx.x * blockDim.x + threadIdx.x;   // grid covers N_NODES*HDIM
    d_AGG[i] = 0.f;
    if (i < N_NODES) { d_cnt[i] = 0; d_cur[i] = 0; }
    if (i < N_GRAPHS) d_gcnt[i] = 0;
}

__global__ void k_hist(const int* __restrict__ ei, const int* __restrict__ batch) {
    int e = blockIdx.x * blockDim.x + threadIdx.x;
    if (e < N_EDGES) atomicAdd(&d_cnt[ei[N_EDGES + e]], 1);
    if (e < N_NODES) atomicAdd(&d_gcnt[batch[e]], 1);
}

__global__ void k_scan() {
    __shared__ int part[1024];
    int t = threadIdx.x;
    int v0 = d_cnt[t*4], v1 = d_cnt[t*4+1], v2 = d_cnt[t*4+2], v3 = d_cnt[t*4+3];
    int s = v0 + v1 + v2 + v3;
    part[t] = s;
    __syncthreads();
    for (int d = 1; d < 1024; d <<= 1) {
        int add = (t >= d) ? part[t - d] : 0;
        __syncthreads();
        part[t] += add;
        __syncthreads();
    }
    int excl = part[t] - s;
    d_off[t*4]   = excl;
    d_off[t*4+1] = excl + v0;
    d_off[t*4+2] = excl + v0 + v1;
    d_off[t*4+3] = excl + v0 + v1 + v2;
}

__global__ void k_fill(const int* __restrict__ ei) {
    int e = blockIdx.x * blockDim.x + threadIdx.x;
    if (e < N_EDGES) {
        int d = ei[N_EDGES + e];
        int p = atomicAdd(&d_cur[d], 1);
        d_eperm[d_off[d] + p] = e;
    }
}

// ---------------- edge MLP for all 3 layers in one launch ----------------
__global__ void k_edge_mlp_all(const float* __restrict__ ea,
                               const float* __restrict__ w1a, const float* __restrict__ b1a,
                               const float* __restrict__ w1b, const float* __restrict__ b1b,
                               const float* __restrict__ w1c, const float* __restrict__ b1c) {
    int e = blockIdx.x;
    int o = threadIdx.x;
    int L = blockIdx.y;
    const float* w1 = (L == 0) ? w1a : (L == 1) ? w1b : w1c;
    const float* b1 = (L == 0) ? b1a : (L == 1) ? b1b : b1c;
    float4 a = *(const float4*)&ea[e * 4];
    float v = b1[o] + a.x * w1[o] + a.y * w1[128 + o] + a.z * w1[256 + o] + a.w * w1[384 + o];
    d_Hc[(size_t)L * N_EDGES * HDIM + e * HDIM + o] = fmaxf(v, 0.f);
}

// ---------------- layer-1 permuted w2 (fp32) ----------------
__global__ void k_permw2(const float* __restrict__ w2, const float* __restrict__ b2,
                         int in_c, int KP) {
    int idx = blockIdx.x * blockDim.x + threadIdx.x;
    if (idx >= KP * HDIM) return;
    int j = idx >> 7, o = idx & 127;
    int KI = 128 * in_c;
    float v = 0.f;
    if (j < KI) {
        int k = j / in_c, i = j - k * in_c;
        v = w2[k * (in_c * HDIM) + i * HDIM + o];
    } else if (j < KI + in_c) {
        int i = j - KI;
        v = b2[i * HDIM + o];
    }
    d_W2p[idx] = v;
}

// ---------------- layers 2/3 B matrix: fp16 [o][j], coalesced via smem transpose ----------------
// grid (129, 2): blockIdx.x = k (0..127 = w2 rows, 128 = bias rows), blockIdx.y = layer
__global__ __launch_bounds__(256) void k_permw2_f16(
        const float* __restrict__ w2a, const float* __restrict__ b2a,
        const float* __restrict__ w2b, const float* __restrict__ b2b) {
    __shared__ float tl[32][133];
    int L = blockIdx.y;
    const float* w2 = L ? w2b : w2a;
    const float* b2 = L ? b2b : b2a;
    __half* out = L ? d_Bf3 : d_Bf2;
    int k = blockIdx.x;

    for (int it = 0; it < 4; it++) {
        for (int t = threadIdx.x; t < 32 * 128; t += 256) {
            int ii = t >> 7, o = t & 127;
            int i = it * 32 + ii;
            float v = (k < 128) ? w2[k * 16384 + i * 128 + o] : b2[i * 128 + o];
            tl[ii][o] = v;
        }
        __syncthreads();
        for (int t = threadIdx.x; t < 512; t += 256) {
            int o = t >> 2, g = t & 3;
            __half hv[8];
#pragma unroll
            for (int q = 0; q < 8; q++) hv[q] = __float2half(tl[g * 8 + q][o]);
            int j0 = k * 128 + it * 32 + g * 8;
            *(uint4*)&out[(size_t)o * KP23 + j0] = *(uint4*)hv;
        }
        __syncthreads();
    }
}

// ---------------- layer-1 scatter (fp32, in_c = 3) ----------------
__global__ void k_scatter3(const float* __restrict__ X, const int* __restrict__ ei) {
    constexpr int INC = 3;
    constexpr int KI = 128 * INC;
    constexpr int KIext = KI + INC;
    constexpr int KP = 392;
    __shared__ float sh_h[32 * 128];
    __shared__ float sh_x[32 * INC];
    __shared__ int sh_e[32];

    int n = blockIdx.x;
    int deg = d_cnt[n];
    int off = d_off[n];
    int tid = threadIdx.x;

    int base = 0;
    while (true) {
        int c = deg - base; if (c > 32) c = 32; if (c < 0) c = 0;
        if (tid < c) sh_e[tid] = d_eperm[off + base + tid];
        __syncthreads();
        for (int t = tid; t < c * 128; t += 256) {
            int dd = t >> 7, k = t & 127;
            sh_h[dd * 128 + k] = d_Hc[sh_e[dd] * HDIM + k];
        }
        for (int t = tid; t < c * INC; t += 256) {
            int dd = t / INC, i = t - dd * INC;
            int s = ei[sh_e[dd]];
            sh_x[dd * INC + i] = X[s * INC + i];
        }
        __syncthreads();
        for (int j = tid; j < KP; j += 256) {
            float v = 0.f;
            if (j < KI) {
                int k = j / INC, i = j - k * INC;
                for (int dd = 0; dd < c; dd++)
                    v += sh_h[dd * 128 + k] * sh_x[dd * INC + i];
            } else if (j < KIext) {
                int i = j - KI;
                for (int dd = 0; dd < c; dd++)
                    v += sh_x[dd * INC + i];
            }
            size_t idx = (size_t)n * KP + j;
            if (base == 0) d_M[idx] = v;
            else           d_M[idx] += v;
        }
        __syncthreads();
        base += 32;
        if (base >= deg) break;
    }
}

// ---------------- layer-2/3 scatter -> fp16 hi/lo, 8-wide groups + packed stores ----------------
__global__ __launch_bounds__(256) void k_scatter_f16(const float* __restrict__ X,
                                                     const int* __restrict__ ei,
                                                     const float* __restrict__ Hc) {
    __shared__ float sh_h[32 * 128];
    __shared__ float sh_x[32 * 128];
    __shared__ int sh_e[32];

    int n = blockIdx.x;
    int deg = d_cnt[n];
    int off = d_off[n];
    int tid = threadIdx.x;

    int base = 0;
    while (true) {
        int c = deg - base; if (c > 32) c = 32; if (c < 0) c = 0;
        if (tid < c) sh_e[tid] = d_eperm[off + base + tid];
        __syncthreads();
        for (int t = tid; t < c * 128; t += 256) {
            int dd = t >> 7, k = t & 127;
            sh_h[dd * 128 + k] = Hc[sh_e[dd] * HDIM + k];
            int s = ei[sh_e[dd]];
            sh_x[dd * 128 + k] = X[s * 128 + k];
        }
        __syncthreads();

        for (int g = tid; g < NGROUPS; g += 256) {
            int j0 = g * 8;
            float v[8];
#pragma unroll
            for (int q = 0; q < 8; q++) v[q] = 0.f;

            if (j0 < 16384) {
                int k = j0 >> 7, i0 = j0 & 127;
                for (int dd = 0; dd < c; dd++) {
                    float h = sh_h[dd * 128 + k];
                    float4 xa = *(const float4*)&sh_x[dd * 128 + i0];
                    float4 xb = *(const float4*)&sh_x[dd * 128 + i0 + 4];
                    v[0] += h * xa.x; v[1] += h * xa.y; v[2] += h * xa.z; v[3] += h * xa.w;
                    v[4] += h * xb.x; v[5] += h * xb.y; v[6] += h * xb.z; v[7] += h * xb.w;
                }
            } else {
                int i0 = j0 - 16384;
                for (int dd = 0; dd < c; dd++) {
                    float4 xa = *(const float4*)&sh_x[dd * 128 + i0];
                    float4 xb = *(const float4*)&sh_x[dd * 128 + i0 + 4];
                    v[0] += xa.x; v[1] += xa.y; v[2] += xa.z; v[3] += xa.w;
                    v[4] += xb.x; v[5] += xb.y; v[6] += xb.z; v[7] += xb.w;
                }
            }

            size_t idx = (size_t)n * KP23 + j0;
            if (base != 0) {
                uint4 ph = *(const uint4*)&d_Ah[idx];
                uint4 pl = *(const uint4*)&d_Al[idx];
                const __half2* hp = (const __half2*)&ph;
                const __half2* lp = (const __half2*)&pl;
#pragma unroll
                for (int q = 0; q < 4; q++) {
                    v[2*q]   += __low2float(hp[q])  + __low2float(lp[q]);
                    v[2*q+1] += __high2float(hp[q]) + __high2float(lp[q]);
                }
            }

            __half2 hh[4], ll[4];
#pragma unroll
            for (int q = 0; q < 4; q++) {
                __half a = __float2half(v[2*q]);
                __half b = __float2half(v[2*q+1]);
                hh[q] = __halves2half2(a, b);
                ll[q] = __halves2half2(__float2half(v[2*q]   - __half2float(a)),
                                       __float2half(v[2*q+1] - __half2float(b)));
            }
            *(uint4*)&d_Ah[idx] = *(uint4*)hh;
            *(uint4*)&d_Al[idx] = *(uint4*)ll;
        }
        __syncthreads();
        base += 32;
        if (base >= deg) break;
    }
}

// ---------------- layer-1 fp32 GEMM (small K) ----------------
__global__ __launch_bounds__(256) void k_gemm(int K, int chunk) {
    __shared__ float As[8 * 128];
    __shared__ float Bs[8 * 128];
    int row0 = blockIdx.x * 128;
    int kb = blockIdx.y * chunk;
    int ke = kb + chunk; if (ke > K) ke = K;
    int tid = threadIdx.x;
    int tr = tid >> 4, tc = tid & 15;
    float acc[8][8];
#pragma unroll
    for (int m = 0; m < 8; m++)
#pragma unroll
        for (int n = 0; n < 8; n++) acc[m][n] = 0.f;

    int ar = tid >> 1, ac = (tid & 1) * 4;
    int br = tid >> 5, bc = (tid & 31) * 4;

    for (int k0 = kb; k0 < ke; k0 += 8) {
        float4 av = *(const float4*)&d_M[(size_t)(row0 + ar) * K + k0 + ac];
        float4 bv = *(const float4*)&d_W2p[(k0 + br) * HDIM + bc];
        As[(ac + 0) * 128 + ar] = av.x;
        As[(ac + 1) * 128 + ar] = av.y;
        As[(ac + 2) * 128 + ar] = av.z;
        As[(ac + 3) * 128 + ar] = av.w;
        *(float4*)&Bs[br * 128 + bc] = bv;
        __syncthreads();
#pragma unroll
        for (int kk = 0; kk < 8; kk++) {
            float a[8], b[8];
#pragma unroll
            for (int m = 0; m < 8; m++) a[m] = As[kk * 128 + tr * 8 + m];
#pragma unroll
            for (int n = 0; n < 8; n++) b[n] = Bs[kk * 128 + tc * 8 + n];
#pragma unroll
            for (int m = 0; m < 8; m++)
#pragma unroll
                for (int n = 0; n < 8; n++)
                    acc[m][n] += a[m] * b[n];
        }
        __syncthreads();
    }
#pragma unroll
    for (int m = 0; m < 8; m++) {
        int r = row0 + tr * 8 + m;
#pragma unroll
        for (int n = 0; n < 8; n++)
            atomicAdd(&d_AGG[r * HDIM + tc * 8 + n], acc[m][n]);
    }
}

// ---------------- HMMA GEMM: AGG += (Ah+Al) @ B^T, fp16 2-pass ----------------
// Stage = {Ah, Al, B} tiles of 16 KB = 48 KB; double-buffered.
#define STAGE_SZ 49152
__global__ __launch_bounds__(256, 1) void k_gemm_mma(const __half* __restrict__ Bsrc) {
    extern __shared__ char dynraw[];
    uint32_t tiles = (smem_u32(dynraw) + 1023) & ~1023u;

    int tid = threadIdx.x;
    int wid = tid >> 5, lane = tid & 31;
    int row0 = blockIdx.x * 128;
    int kz = blockIdx.y;
    int wm = (wid & 3) * 32;
    int wn = (wid >> 2) * 64;

    int c0 = (kz * NCHUNK) / KSPLIT;
    int c1 = ((kz + 1) * NCHUNK) / KSPLIT;
    int ncl = c1 - c0;

    int lrow = tid >> 1;
    int lq = (tid & 1) * 4;
    const char* gAh = (const char*)(d_Ah + (size_t)(row0 + lrow) * KP23);
    const char* gAl = (const char*)(d_Al + (size_t)(row0 + lrow) * KP23);
    const char* gB  = (const char*)(Bsrc + (size_t)lrow * KP23);

    float acc[2][8][4];
#pragma unroll
    for (int mt = 0; mt < 2; mt++)
#pragma unroll
        for (int n8 = 0; n8 < 8; n8++)
#pragma unroll
            for (int q = 0; q < 4; q++) acc[mt][n8][q] = 0.f;

    uint32_t st_off[4];
#pragma unroll
    for (int q = 0; q < 4; q++)
        st_off[q] = SW128((uint32_t)(lrow * 128 + (lq + q) * 16));

    auto load_stage = [&](int cc, int s) {
        uint32_t sb = tiles + s * STAGE_SZ;
        int kb = (c0 + cc) * 128;
        const char* srcs[3] = { gAh + kb, gAl + kb, gB + kb };
#pragma unroll
        for (int t = 0; t < 3; t++) {
            uint32_t tb = sb + t * 16384;
#pragma unroll
            for (int q = 0; q < 4; q++)
                cpa16(tb + st_off[q], srcs[t] + (lq + q) * 16);
        }
    };

    load_stage(0, 0); CPA_COMMIT();

    for (int cc = 0; cc < ncl; cc++) {
        int s = cc & 1;
        if (cc + 1 < ncl) {
            load_stage(cc + 1, s ^ 1); CPA_COMMIT();
            CPA_WAIT1();
        } else {
            CPA_WAIT0();
        }
        __syncthreads();

        uint32_t sb = tiles + s * STAGE_SZ;
#pragma unroll
        for (int kk = 0; kk < 4; kk++) {
            uint32_t ah[2][4], al[2][4], b[4][4];
#pragma unroll
            for (int mt = 0; mt < 2; mt++) {
                uint32_t off = (uint32_t)((wm + mt * 16 + (lane & 15)) * 128
                                          + kk * 32 + (lane >> 4) * 16);
                uint32_t sw = SW128(off);
                ldsm_x4(ah[mt], sb + sw);
                ldsm_x4(al[mt], sb + 16384 + sw);
            }
#pragma unroll
            for (int nt = 0; nt < 4; nt++) {
                uint32_t off = (uint32_t)((wn + nt * 16 + (lane & 7) + ((lane >> 4) & 1) * 8) * 128
                                          + kk * 32 + ((lane >> 3) & 1) * 16);
                uint32_t sw = SW128(off);
                ldsm_x4(b[nt], sb + 32768 + sw);
            }
#pragma unroll
            for (int mt = 0; mt < 2; mt++)
#pragma unroll
                for (int n8 = 0; n8 < 8; n8++) {
                    int nt = n8 >> 1, h = (n8 & 1) * 2;
                    mma_f16(acc[mt][n8], ah[mt], b[nt][h], b[nt][h + 1]);
                    mma_f16(acc[mt][n8], al[mt], b[nt][h], b[nt][h + 1]);
                }
        }
        __syncthreads();
    }

#pragma unroll
    for (int mt = 0; mt < 2; mt++) {
        int r = row0 + wm + mt * 16 + (lane >> 2);
#pragma unroll
        for (int n8 = 0; n8 < 8; n8++) {
            int cb = wn + n8 * 8 + (lane & 3) * 2;
            atomicAdd(&d_AGG[r * HDIM + cb],           acc[mt][n8][0]);
            atomicAdd(&d_AGG[r * HDIM + cb + 1],       acc[mt][n8][1]);
            atomicAdd(&d_AGG[(r + 8) * HDIM + cb],     acc[mt][n8][2]);
            atomicAdd(&d_AGG[(r + 8) * HDIM + cb + 1], acc[mt][n8][3]);
        }
    }
}

// ---------------- combine (+ re-zero AGG for the next layer) ----------------
template <int INC, int ACT>
__global__ void k_combine(const float* __restrict__ Xin,
                          const float* __restrict__ root,
                          const float* __restrict__ bias,
                          const float* __restrict__ lng,
                          const float* __restrict__ lnb,
                          float* __restrict__ Xout) {
    __shared__ float shx[INC];
    __shared__ float red[4];
    int n = blockIdx.x;
    int o = threadIdx.x;
    for (int i = o; i < INC; i += 128) shx[i] = Xin[n * INC + i];
    __syncthreads();

    float r = bias[o];
#pragma unroll 4
    for (int i = 0; i < INC; i++) r += shx[i] * root[i * HDIM + o];

    float cnt = (float)max(d_cnt[n], 1);
    float pre = d_AGG[n * HDIM + o] / cnt + r;
    d_AGG[n * HDIM + o] = 0.f;           // ready for next layer's atomics

    float v = pre;
    for (int s = 16; s; s >>= 1) v += __shfl_xor_sync(0xffffffffu, v, s);
    if ((o & 31) == 0) red[o >> 5] = v;
    __syncthreads();
    float mean = (red[0] + red[1] + red[2] + red[3]) * (1.f / 128.f);
    __syncthreads();

    float cen = pre - mean;
    float v2 = cen * cen;
    for (int s = 16; s; s >>= 1) v2 += __shfl_xor_sync(0xffffffffu, v2, s);
    if ((o & 31) == 0) red[o >> 5] = v2;
    __syncthreads();
    float var = (red[0] + red[1] + red[2] + red[3]) * (1.f / 128.f);

    float y = cen * rsqrtf(var + LN_EPS) * lng[o] + lnb[o];
    if (ACT == 0)      y = fmaxf(y, 0.f);
    else if (ACT == 1) y = (y > 0.f) ? y : expm1f(y);
    else               y = (y >= 0.f) ? y : 0.01f * y;
    Xout[n * HDIM + o] = y;
}

// ---------------- pool (mean + max per graph) + final linear ----------------
__global__ void k_pool(const float* __restrict__ X,
                       const float* __restrict__ ct,
                       const float* __restrict__ ls,
                       const float* __restrict__ lw,
                       const float* __restrict__ lb,
                       float* __restrict__ out) {
    __shared__ float cat[261];
    int g = blockIdx.x;
    int o = threadIdx.x;
    int start = 0;
    for (int q = 0; q < g; q++) start += d_gcnt[q];
    int c = d_gcnt[g];
    float s = 0.f, mx = -INFINITY;
    for (int t = 0; t < c; t++) {
        float v = X[(size_t)(start + t) * HDIM + o];
        s += v;
        mx = fmaxf(mx, v);
    }
    cat[o]       = s / fmaxf((float)c, 1.f);
    cat[128 + o] = (c > 0) ? mx : 0.f;
    if (o < 4)  cat[256 + o] = ct[g * 4 + o];
    if (o == 4) cat[260] = ls[g];
    __syncthreads();
    if (o < 2) {
        float acc = lb[o];
        for (int j = 0; j < 261; j++) acc += cat[j] * lw[j * 2 + o];
        out[g * 2 + o] = acc;
    }
}

// ---------------- launch ----------------
extern "C" void kernel_launch(void* const* d_in, const int* in_sizes, int n_in,
                              void* d_out, int out_size) {
    const float* x     = (const float*)d_in[0];
    const int*   ei    = (const int*)  d_in[1];
    const float* ea    = (const float*)d_in[2];
    const int*   batch = (const int*)  d_in[3];
    const float* ct    = (const float*)d_in[4];
    const float* ls    = (const float*)d_in[5];

    const float* w1[3]   = {(const float*)d_in[6],  (const float*)d_in[12], (const float*)d_in[18]};
    const float* b1[3]   = {(const float*)d_in[7],  (const float*)d_in[13], (const float*)d_in[19]};
    const float* w2[3]   = {(const float*)d_in[8],  (const float*)d_in[14], (const float*)d_in[20]};
    const float* b2[3]   = {(const float*)d_in[9],  (const float*)d_in[15], (const float*)d_in[21]};
    const float* root[3] = {(const float*)d_in[10], (const float*)d_in[16], (const float*)d_in[22]};
    const float* bias[3] = {(const float*)d_in[11], (const float*)d_in[17], (const float*)d_in[23]};

    const float* lng[3] = {(const float*)d_in[24], (const float*)d_in[26], (const float*)d_in[28]};
    const float* lnb[3] = {(const float*)d_in[25], (const float*)d_in[27], (const float*)d_in[29]};
    const float* lw = (const float*)d_in[30];
    const float* lb = (const float*)d_in[31];
    float* out = (float*)d_out;

    float *pXA, *pXB, *pHc;
    __half *pBf2, *pBf3;
    cudaGetSymbolAddress((void**)&pXA, d_XA);
    cudaGetSymbolAddress((void**)&pXB, d_XB);
    cudaGetSymbolAddress((void**)&pHc, d_Hc);
    cudaGetSymbolAddress((void**)&pBf2, d_Bf2);
    cudaGetSymbolAddress((void**)&pBf3, d_Bf3);

    const int GEMM_SMEM = 2 * STAGE_SZ + 1024;
    cudaFuncSetAttribute(k_gemm_mma, cudaFuncAttributeMaxDynamicSharedMemorySize, GEMM_SMEM);

    // init + CSR
    k_zero_all<<<512, 1024>>>();
    k_hist<<<64, 256>>>(ei, batch);
    k_scan<<<1, 1024>>>();
    k_fill<<<64, 256>>>(ei);

    // precompute all edge MLPs + permuted weights (independent of layer results)
    k_edge_mlp_all<<<dim3(N_EDGES, 3), 128>>>(ea, w1[0], b1[0], w1[1], b1[1], w1[2], b1[2]);
    k_permw2<<<(KP_L1 * HDIM + 255) / 256, 256>>>(w2[0], b2[0], 3, KP_L1);
    k_permw2_f16<<<dim3(129, 2), 256>>>(w2[1], b2[1], w2[2], b2[2]);

    // ---- layer 1 (in_c = 3, relu) — fp32 SIMT ----
    k_scatter3<<<N_NODES, 256>>>(x, ei);
    k_gemm<<<dim3(32, 7), 256>>>(KP_L1, 56);
    k_combine<3, 0><<<N_NODES, 128>>>(x, root[0], bias[0], lng[0], lnb[0], pXA);

    // ---- layer 2 (elu) — fp16 2-pass HMMA ----
    k_scatter_f16<<<N_NODES, 256>>>(pXA, ei, pHc + (size_t)1 * N_EDGES * HDIM);
    k_gemm_mma<<<dim3(32, KSPLIT), 256, GEMM_SMEM>>>(pBf2);
    k_combine<128, 1><<<N_NODES, 128>>>(pXA, root[1], bias[1], lng[1], lnb[1], pXB);

    // ---- layer 3 (leaky_relu) — fp16 2-pass HMMA ----
    k_scatter_f16<<<N_NODES, 256>>>(pXB, ei, pHc + (size_t)2 * N_EDGES * HDIM);
    k_gemm_mma<<<dim3(32, KSPLIT), 256, GEMM_SMEM>>>(pBf3);
    k_combine<128, 2><<<N_NODES, 128>>>(pXB, root[2], bias[2], lng[2], lnb[2], pXA);

    // ---- pooling + final linear ----
    k_pool<<<N_GRAPHS, 128>>>(pXA, ct, ls, lw, lb, out);
}

// round 6
// speedup vs baseline: 2.8599x; 1.2443x over previous
#include <cuda_runtime.h>
#include <cuda_bf16.h>
#include <cuda_fp16.h>
#include <math.h>
#include <stdint.h>

#define N_NODES 4096
#define N_EDGES 16384
#define N_GRAPHS 16
#define HDIM 128
#define LN_EPS 1e-5f

// layer1: KI=384, +3 bias rows = 387 -> pad 392 (fp32 SIMT path)
// layer2/3: KI=16384, +128 bias rows = 16512 (HMMA fp16 1-pass path)
static const int KP_L1 = 392;
#define KP23 16512
#define NCHUNK 258          // 16512 / 64
#define KSPLIT 4
#define NGROUPS 2064        // 16512 / 8

// ---------------- device scratch ----------------
__device__ float d_M[(size_t)N_NODES * KP_L1];
__device__ float d_W2p[KP_L1 * HDIM];
__device__ __half d_Af[(size_t)N_NODES * KP23];      // fp16(M)
__device__ __half d_Bf2[(size_t)HDIM * KP23];        // fp16(W2p^T) layer 2
__device__ __half d_Bf3[(size_t)HDIM * KP23];        // fp16(W2p^T) layer 3
__device__ float d_Hc[(size_t)3 * N_EDGES * HDIM];   // edge MLP out, all layers
__device__ float d_XA[N_NODES * HDIM];
__device__ float d_XB[N_NODES * HDIM];
__device__ float d_AGG[N_NODES * HDIM];
__device__ int d_cnt[N_NODES];
__device__ int d_off[N_NODES];
__device__ int d_cur[N_NODES];
__device__ int d_eperm[N_EDGES];
__device__ int d_gcnt[N_GRAPHS];

// ---------------- PTX helpers (baseline ISA only) ----------------
__device__ __forceinline__ uint32_t smem_u32(const void* p) {
    uint32_t a;
    asm("{ .reg .u64 t; cvta.to.shared.u64 t, %1; cvt.u32.u64 %0, t; }" : "=r"(a) : "l"(p));
    return a;
}
__device__ __forceinline__ void cpa16(uint32_t smem_addr, const void* g) {
    asm volatile("cp.async.cg.shared.global [%0], [%1], 16;" :: "r"(smem_addr), "l"(g));
}
#define CPA_COMMIT() asm volatile("cp.async.commit_group;" ::: "memory")
#define CPA_WAIT0()  asm volatile("cp.async.wait_group 0;" ::: "memory")
#define CPA_WAIT1()  asm volatile("cp.async.wait_group 1;" ::: "memory")

__device__ __forceinline__ void ldsm_x4(uint32_t* r, uint32_t addr) {
    asm volatile("ldmatrix.sync.aligned.m8n8.x4.shared.b16 {%0,%1,%2,%3}, [%4];"
                 : "=r"(r[0]), "=r"(r[1]), "=r"(r[2]), "=r"(r[3]) : "r"(addr));
}
__device__ __forceinline__ void mma_f16(float* c, const uint32_t* a, uint32_t b0, uint32_t b1) {
    asm volatile("mma.sync.aligned.m16n8k16.row.col.f32.f16.f16.f32 "
                 "{%0,%1,%2,%3}, {%4,%5,%6,%7}, {%8,%9}, {%0,%1,%2,%3};"
                 : "+f"(c[0]), "+f"(c[1]), "+f"(c[2]), "+f"(c[3])
                 : "r"(a[0]), "r"(a[1]), "r"(a[2]), "r"(a[3]), "r"(b0), "r"(b1));
}
#define SW128(off) ((off) ^ (((off) >> 3) & 0x70))

// ---------------- init: zero AGG + counters (one launch) ----------------
__global__ void k_zero_all() {
    int i = blockIdx.x * blockDim.x + threadIdx.x;   // grid covers N_NODES*HDIM
    d_AGG[i] = 0.f;
    if (i < N_NODES) { d_cnt[i] = 0; d_cur[i] = 0; }
    if (i < N_GRAPHS) d_gcnt[i] = 0;
}

__global__ void k_hist(const int* __restrict__ ei, const int* __restrict__ batch) {
    int e = blockIdx.x * blockDim.x + threadIdx.x;
    if (e < N_EDGES) atomicAdd(&d_cnt[ei[N_EDGES + e]], 1);
    if (e < N_NODES) atomicAdd(&d_gcnt[batch[e]], 1);
}

__global__ void k_scan() {
    __shared__ int part[1024];
    int t = threadIdx.x;
    int v0 = d_cnt[t*4], v1 = d_cnt[t*4+1], v2 = d_cnt[t*4+2], v3 = d_cnt[t*4+3];
    int s = v0 + v1 + v2 + v3;
    part[t] = s;
    __syncthreads();
    for (int d = 1; d < 1024; d <<= 1) {
        int add = (t >= d) ? part[t - d] : 0;
        __syncthreads();
        part[t] += add;
        __syncthreads();
    }
    int excl = part[t] - s;
    d_off[t*4]   = excl;
    d_off[t*4+1] = excl + v0;
    d_off[t*4+2] = excl + v0 + v1;
    d_off[t*4+3] = excl + v0 + v1 + v2;
}

__global__ void k_fill(const int* __restrict__ ei) {
    int e = blockIdx.x * blockDim.x + threadIdx.x;
    if (e < N_EDGES) {
        int d = ei[N_EDGES + e];
        int p = atomicAdd(&d_cur[d], 1);
        d_eperm[d_off[d] + p] = e;
    }
}

// ---------------- edge MLP for all 3 layers in one launch ----------------
__global__ void k_edge_mlp_all(const float* __restrict__ ea,
                               const float* __restrict__ w1a, const float* __restrict__ b1a,
                               const float* __restrict__ w1b, const float* __restrict__ b1b,
                               const float* __restrict__ w1c, const float* __restrict__ b1c) {
    int e = blockIdx.x;
    int o = threadIdx.x;
    int L = blockIdx.y;
    const float* w1 = (L == 0) ? w1a : (L == 1) ? w1b : w1c;
    const float* b1 = (L == 0) ? b1a : (L == 1) ? b1b : b1c;
    float4 a = *(const float4*)&ea[e * 4];
    float v = b1[o] + a.x * w1[o] + a.y * w1[128 + o] + a.z * w1[256 + o] + a.w * w1[384 + o];
    d_Hc[(size_t)L * N_EDGES * HDIM + e * HDIM + o] = fmaxf(v, 0.f);
}

// ---------------- layer-1 permuted w2 (fp32) ----------------
__global__ void k_permw2(const float* __restrict__ w2, const float* __restrict__ b2,
                         int in_c, int KP) {
    int idx = blockIdx.x * blockDim.x + threadIdx.x;
    if (idx >= KP * HDIM) return;
    int j = idx >> 7, o = idx & 127;
    int KI = 128 * in_c;
    float v = 0.f;
    if (j < KI) {
        int k = j / in_c, i = j - k * in_c;
        v = w2[k * (in_c * HDIM) + i * HDIM + o];
    } else if (j < KI + in_c) {
        int i = j - KI;
        v = b2[i * HDIM + o];
    }
    d_W2p[idx] = v;
}

// ---------------- layers 2/3 B matrix: fp16 [o][j], coalesced via smem transpose ----------------
__global__ __launch_bounds__(256) void k_permw2_f16(
        const float* __restrict__ w2a, const float* __restrict__ b2a,
        const float* __restrict__ w2b, const float* __restrict__ b2b) {
    __shared__ float tl[32][133];
    int L = blockIdx.y;
    const float* w2 = L ? w2b : w2a;
    const float* b2 = L ? b2b : b2a;
    __half* out = L ? d_Bf3 : d_Bf2;
    int k = blockIdx.x;

    for (int it = 0; it < 4; it++) {
        for (int t = threadIdx.x; t < 32 * 128; t += 256) {
            int ii = t >> 7, o = t & 127;
            int i = it * 32 + ii;
            float v = (k < 128) ? w2[k * 16384 + i * 128 + o] : b2[i * 128 + o];
            tl[ii][o] = v;
        }
        __syncthreads();
        for (int t = threadIdx.x; t < 512; t += 256) {
            int o = t >> 2, g = t & 3;
            __half hv[8];
#pragma unroll
            for (int q = 0; q < 8; q++) hv[q] = __float2half(tl[g * 8 + q][o]);
            int j0 = k * 128 + it * 32 + g * 8;
            *(uint4*)&out[(size_t)o * KP23 + j0] = *(uint4*)hv;
        }
        __syncthreads();
    }
}

// ---------------- layer-1 scatter (fp32, in_c = 3) ----------------
__global__ void k_scatter3(const float* __restrict__ X, const int* __restrict__ ei) {
    constexpr int INC = 3;
    constexpr int KI = 128 * INC;
    constexpr int KIext = KI + INC;
    constexpr int KP = 392;
    __shared__ float sh_h[32 * 128];
    __shared__ float sh_x[32 * INC];
    __shared__ int sh_e[32];

    int n = blockIdx.x;
    int deg = d_cnt[n];
    int off = d_off[n];
    int tid = threadIdx.x;

    int base = 0;
    while (true) {
        int c = deg - base; if (c > 32) c = 32; if (c < 0) c = 0;
        if (tid < c) sh_e[tid] = d_eperm[off + base + tid];
        __syncthreads();
        for (int t = tid; t < c * 128; t += 256) {
            int dd = t >> 7, k = t & 127;
            sh_h[dd * 128 + k] = d_Hc[sh_e[dd] * HDIM + k];
        }
        for (int t = tid; t < c * INC; t += 256) {
            int dd = t / INC, i = t - dd * INC;
            int s = ei[sh_e[dd]];
            sh_x[dd * INC + i] = X[s * INC + i];
        }
        __syncthreads();
        for (int j = tid; j < KP; j += 256) {
            float v = 0.f;
            if (j < KI) {
                int k = j / INC, i = j - k * INC;
                for (int dd = 0; dd < c; dd++)
                    v += sh_h[dd * 128 + k] * sh_x[dd * INC + i];
            } else if (j < KIext) {
                int i = j - KI;
                for (int dd = 0; dd < c; dd++)
                    v += sh_x[dd * INC + i];
            }
            size_t idx = (size_t)n * KP + j;
            if (base == 0) d_M[idx] = v;
            else           d_M[idx] += v;
        }
        __syncthreads();
        base += 32;
        if (base >= deg) break;
    }
}

// ---------------- layer-2/3 scatter -> fp16, 8-wide groups + packed stores ----------------
__global__ __launch_bounds__(256) void k_scatter_f16(const float* __restrict__ X,
                                                     const int* __restrict__ ei,
                                                     const float* __restrict__ Hc) {
    __shared__ float sh_h[32 * 128];
    __shared__ float sh_x[32 * 128];
    __shared__ int sh_e[32];

    int n = blockIdx.x;
    int deg = d_cnt[n];
    int off = d_off[n];
    int tid = threadIdx.x;

    int base = 0;
    while (true) {
        int c = deg - base; if (c > 32) c = 32; if (c < 0) c = 0;
        if (tid < c) sh_e[tid] = d_eperm[off + base + tid];
        __syncthreads();
        for (int t = tid; t < c * 128; t += 256) {
            int dd = t >> 7, k = t & 127;
            sh_h[dd * 128 + k] = Hc[sh_e[dd] * HDIM + k];
            int s = ei[sh_e[dd]];
            sh_x[dd * 128 + k] = X[s * 128 + k];
        }
        __syncthreads();

        for (int g = tid; g < NGROUPS; g += 256) {
            int j0 = g * 8;
            float v[8];
#pragma unroll
            for (int q = 0; q < 8; q++) v[q] = 0.f;

            if (j0 < 16384) {
                int k = j0 >> 7, i0 = j0 & 127;
                for (int dd = 0; dd < c; dd++) {
                    float h = sh_h[dd * 128 + k];
                    float4 xa = *(const float4*)&sh_x[dd * 128 + i0];
                    float4 xb = *(const float4*)&sh_x[dd * 128 + i0 + 4];
                    v[0] += h * xa.x; v[1] += h * xa.y; v[2] += h * xa.z; v[3] += h * xa.w;
                    v[4] += h * xb.x; v[5] += h * xb.y; v[6] += h * xb.z; v[7] += h * xb.w;
                }
            } else {
                int i0 = j0 - 16384;
                for (int dd = 0; dd < c; dd++) {
                    float4 xa = *(const float4*)&sh_x[dd * 128 + i0];
                    float4 xb = *(const float4*)&sh_x[dd * 128 + i0 + 4];
                    v[0] += xa.x; v[1] += xa.y; v[2] += xa.z; v[3] += xa.w;
                    v[4] += xb.x; v[5] += xb.y; v[6] += xb.z; v[7] += xb.w;
                }
            }

            size_t idx = (size_t)n * KP23 + j0;
            if (base != 0) {       // rare multi-pass: accumulate previous stored value
                uint4 ph = *(const uint4*)&d_Af[idx];
                const __half2* hp = (const __half2*)&ph;
#pragma unroll
                for (int q = 0; q < 4; q++) {
                    v[2*q]   += __low2float(hp[q]);
                    v[2*q+1] += __high2float(hp[q]);
                }
            }

            __half2 hh[4];
#pragma unroll
            for (int q = 0; q < 4; q++)
                hh[q] = __halves2half2(__float2half(v[2*q]), __float2half(v[2*q+1]));
            *(uint4*)&d_Af[idx] = *(uint4*)hh;
        }
        __syncthreads();
        base += 32;
        if (base >= deg) break;
    }
}

// ---------------- layer-1 fp32 GEMM (small K) ----------------
__global__ __launch_bounds__(256) void k_gemm(int K, int chunk) {
    __shared__ float As[8 * 128];
    __shared__ float Bs[8 * 128];
    int row0 = blockIdx.x * 128;
    int kb = blockIdx.y * chunk;
    int ke = kb + chunk; if (ke > K) ke = K;
    int tid = threadIdx.x;
    int tr = tid >> 4, tc = tid & 15;
    float acc[8][8];
#pragma unroll
    for (int m = 0; m < 8; m++)
#pragma unroll
        for (int n = 0; n < 8; n++) acc[m][n] = 0.f;

    int ar = tid >> 1, ac = (tid & 1) * 4;
    int br = tid >> 5, bc = (tid & 31) * 4;

    for (int k0 = kb; k0 < ke; k0 += 8) {
        float4 av = *(const float4*)&d_M[(size_t)(row0 + ar) * K + k0 + ac];
        float4 bv = *(const float4*)&d_W2p[(k0 + br) * HDIM + bc];
        As[(ac + 0) * 128 + ar] = av.x;
        As[(ac + 1) * 128 + ar] = av.y;
        As[(ac + 2) * 128 + ar] = av.z;
        As[(ac + 3) * 128 + ar] = av.w;
        *(float4*)&Bs[br * 128 + bc] = bv;
        __syncthreads();
#pragma unroll
        for (int kk = 0; kk < 8; kk++) {
            float a[8], b[8];
#pragma unroll
            for (int m = 0; m < 8; m++) a[m] = As[kk * 128 + tr * 8 + m];
#pragma unroll
            for (int n = 0; n < 8; n++) b[n] = Bs[kk * 128 + tc * 8 + n];
#pragma unroll
            for (int m = 0; m < 8; m++)
#pragma unroll
                for (int n = 0; n < 8; n++)
                    acc[m][n] += a[m] * b[n];
        }
        __syncthreads();
    }
#pragma unroll
    for (int m = 0; m < 8; m++) {
        int r = row0 + tr * 8 + m;
#pragma unroll
        for (int n = 0; n < 8; n++)
            atomicAdd(&d_AGG[r * HDIM + tc * 8 + n], acc[m][n]);
    }
}

// ---------------- HMMA GEMM: AGG += A @ B^T, fp16 single-pass ----------------
// Stage = {A, B} tiles of 16 KB = 32 KB; double-buffered.
#define STAGE_SZ 32768
__global__ __launch_bounds__(256, 1) void k_gemm_mma(const __half* __restrict__ Bsrc) {
    extern __shared__ char dynraw[];
    uint32_t tiles = (smem_u32(dynraw) + 1023) & ~1023u;

    int tid = threadIdx.x;
    int wid = tid >> 5, lane = tid & 31;
    int row0 = blockIdx.x * 128;
    int kz = blockIdx.y;
    int wm = (wid & 3) * 32;
    int wn = (wid >> 2) * 64;

    int c0 = (kz * NCHUNK) / KSPLIT;
    int c1 = ((kz + 1) * NCHUNK) / KSPLIT;
    int ncl = c1 - c0;

    int lrow = tid >> 1;
    int lq = (tid & 1) * 4;
    const char* gA = (const char*)(d_Af + (size_t)(row0 + lrow) * KP23);
    const char* gB = (const char*)(Bsrc + (size_t)lrow * KP23);

    float acc[2][8][4];
#pragma unroll
    for (int mt = 0; mt < 2; mt++)
#pragma unroll
        for (int n8 = 0; n8 < 8; n8++)
#pragma unroll
            for (int q = 0; q < 4; q++) acc[mt][n8][q] = 0.f;

    uint32_t st_off[4];
#pragma unroll
    for (int q = 0; q < 4; q++)
        st_off[q] = SW128((uint32_t)(lrow * 128 + (lq + q) * 16));

    auto load_stage = [&](int cc, int s) {
        uint32_t sb = tiles + s * STAGE_SZ;
        int kb = (c0 + cc) * 128;
        const char* srcs[2] = { gA + kb, gB + kb };
#pragma unroll
        for (int t = 0; t < 2; t++) {
            uint32_t tb = sb + t * 16384;
#pragma unroll
            for (int q = 0; q < 4; q++)
                cpa16(tb + st_off[q], srcs[t] + (lq + q) * 16);
        }
    };

    load_stage(0, 0); CPA_COMMIT();

    for (int cc = 0; cc < ncl; cc++) {
        int s = cc & 1;
        if (cc + 1 < ncl) {
            load_stage(cc + 1, s ^ 1); CPA_COMMIT();
            CPA_WAIT1();
        } else {
            CPA_WAIT0();
        }
        __syncthreads();

        uint32_t sb = tiles + s * STAGE_SZ;
#pragma unroll
        for (int kk = 0; kk < 4; kk++) {
            uint32_t a[2][4], b[4][4];
#pragma unroll
            for (int mt = 0; mt < 2; mt++) {
                uint32_t off = (uint32_t)((wm + mt * 16 + (lane & 15)) * 128
                                          + kk * 32 + (lane >> 4) * 16);
                ldsm_x4(a[mt], sb + SW128(off));
            }
#pragma unroll
            for (int nt = 0; nt < 4; nt++) {
                uint32_t off = (uint32_t)((wn + nt * 16 + (lane & 7) + ((lane >> 4) & 1) * 8) * 128
                                          + kk * 32 + ((lane >> 3) & 1) * 16);
                ldsm_x4(b[nt], sb + 16384 + SW128(off));
            }
#pragma unroll
            for (int mt = 0; mt < 2; mt++)
#pragma unroll
                for (int n8 = 0; n8 < 8; n8++) {
                    int nt = n8 >> 1, h = (n8 & 1) * 2;
                    mma_f16(acc[mt][n8], a[mt], b[nt][h], b[nt][h + 1]);
                }
        }
        __syncthreads();
    }

#pragma unroll
    for (int mt = 0; mt < 2; mt++) {
        int r = row0 + wm + mt * 16 + (lane >> 2);
#pragma unroll
        for (int n8 = 0; n8 < 8; n8++) {
            int cb = wn + n8 * 8 + (lane & 3) * 2;
            atomicAdd(&d_AGG[r * HDIM + cb],           acc[mt][n8][0]);
            atomicAdd(&d_AGG[r * HDIM + cb + 1],       acc[mt][n8][1]);
            atomicAdd(&d_AGG[(r + 8) * HDIM + cb],     acc[mt][n8][2]);
            atomicAdd(&d_AGG[(r + 8) * HDIM + cb + 1], acc[mt][n8][3]);
        }
    }
}

// ---------------- combine (+ re-zero AGG for the next layer) ----------------
template <int INC, int ACT>
__global__ void k_combine(const float* __restrict__ Xin,
                          const float* __restrict__ root,
                          const float* __restrict__ bias,
                          const float* __restrict__ lng,
                          const float* __restrict__ lnb,
                          float* __restrict__ Xout) {
    __shared__ float shx[INC];
    __shared__ float red[4];
    int n = blockIdx.x;
    int o = threadIdx.x;
    for (int i = o; i < INC; i += 128) shx[i] = Xin[n * INC + i];
    __syncthreads();

    float r = bias[o];
#pragma unroll 4
    for (int i = 0; i < INC; i++) r += shx[i] * root[i * HDIM + o];

    float cnt = (float)max(d_cnt[n], 1);
    float pre = d_AGG[n * HDIM + o] / cnt + r;
    d_AGG[n * HDIM + o] = 0.f;           // ready for next layer's atomics

    float v = pre;
    for (int s = 16; s; s >>= 1) v += __shfl_xor_sync(0xffffffffu, v, s);
    if ((o & 31) == 0) red[o >> 5] = v;
    __syncthreads();
    float mean = (red[0] + red[1] + red[2] + red[3]) * (1.f / 128.f);
    __syncthreads();

    float cen = pre - mean;
    float v2 = cen * cen;
    for (int s = 16; s; s >>= 1) v2 += __shfl_xor_sync(0xffffffffu, v2, s);
    if ((o & 31) == 0) red[o >> 5] = v2;
    __syncthreads();
    float var = (red[0] + red[1] + red[2] + red[3]) * (1.f / 128.f);

    float y = cen * rsqrtf(var + LN_EPS) * lng[o] + lnb[o];
    if (ACT == 0)      y = fmaxf(y, 0.f);
    else if (ACT == 1) y = (y > 0.f) ? y : expm1f(y);
    else               y = (y >= 0.f) ? y : 0.01f * y;
    Xout[n * HDIM + o] = y;
}

// ---------------- pool (mean + max per graph) + final linear ----------------
__global__ void k_pool(const float* __restrict__ X,
                       const float* __restrict__ ct,
                       const float* __restrict__ ls,
                       const float* __restrict__ lw,
                       const float* __restrict__ lb,
                       float* __restrict__ out) {
    __shared__ float cat[261];
    int g = blockIdx.x;
    int o = threadIdx.x;
    int start = 0;
    for (int q = 0; q < g; q++) start += d_gcnt[q];
    int c = d_gcnt[g];
    float s = 0.f, mx = -INFINITY;
    for (int t = 0; t < c; t++) {
        float v = X[(size_t)(start + t) * HDIM + o];
        s += v;
        mx = fmaxf(mx, v);
    }
    cat[o]       = s / fmaxf((float)c, 1.f);
    cat[128 + o] = (c > 0) ? mx : 0.f;
    if (o < 4)  cat[256 + o] = ct[g * 4 + o];
    if (o == 4) cat[260] = ls[g];
    __syncthreads();
    if (o < 2) {
        float acc = lb[o];
        for (int j = 0; j < 261; j++) acc += cat[j] * lw[j * 2 + o];
        out[g * 2 + o] = acc;
    }
}

// ---------------- launch ----------------
extern "C" void kernel_launch(void* const* d_in, const int* in_sizes, int n_in,
                              void* d_out, int out_size) {
    const float* x     = (const float*)d_in[0];
    const int*   ei    = (const int*)  d_in[1];
    const float* ea    = (const float*)d_in[2];
    const int*   batch = (const int*)  d_in[3];
    const float* ct    = (const float*)d_in[4];
    const float* ls    = (const float*)d_in[5];

    const float* w1[3]   = {(const float*)d_in[6],  (const float*)d_in[12], (const float*)d_in[18]};
    const float* b1[3]   = {(const float*)d_in[7],  (const float*)d_in[13], (const float*)d_in[19]};
    const float* w2[3]   = {(const float*)d_in[8],  (const float*)d_in[14], (const float*)d_in[20]};
    const float* b2[3]   = {(const float*)d_in[9],  (const float*)d_in[15], (const float*)d_in[21]};
    const float* root[3] = {(const float*)d_in[10], (const float*)d_in[16], (const float*)d_in[22]};
    const float* bias[3] = {(const float*)d_in[11], (const float*)d_in[17], (const float*)d_in[23]};

    const float* lng[3] = {(const float*)d_in[24], (const float*)d_in[26], (const float*)d_in[28]};
    const float* lnb[3] = {(const float*)d_in[25], (const float*)d_in[27], (const float*)d_in[29]};
    const float* lw = (const float*)d_in[30];
    const float* lb = (const float*)d_in[31];
    float* out = (float*)d_out;

    float *pXA, *pXB, *pHc;
    __half *pBf2, *pBf3;
    cudaGetSymbolAddress((void**)&pXA, d_XA);
    cudaGetSymbolAddress((void**)&pXB, d_XB);
    cudaGetSymbolAddress((void**)&pHc, d_Hc);
    cudaGetSymbolAddress((void**)&pBf2, d_Bf2);
    cudaGetSymbolAddress((void**)&pBf3, d_Bf3);

    const int GEMM_SMEM = 2 * STAGE_SZ + 1024;
    cudaFuncSetAttribute(k_gemm_mma, cudaFuncAttributeMaxDynamicSharedMemorySize, GEMM_SMEM);

    // init + CSR
    k_zero_all<<<512, 1024>>>();
    k_hist<<<64, 256>>>(ei, batch);
    k_scan<<<1, 1024>>>();
    k_fill<<<64, 256>>>(ei);

    // precompute all edge MLPs + permuted weights (independent of layer results)
    k_edge_mlp_all<<<dim3(N_EDGES, 3), 128>>>(ea, w1[0], b1[0], w1[1], b1[1], w1[2], b1[2]);
    k_permw2<<<(KP_L1 * HDIM + 255) / 256, 256>>>(w2[0], b2[0], 3, KP_L1);
    k_permw2_f16<<<dim3(129, 2), 256>>>(w2[1], b2[1], w2[2], b2[2]);

    // ---- layer 1 (in_c = 3, relu) — fp32 SIMT ----
    k_scatter3<<<N_NODES, 256>>>(x, ei);
    k_gemm<<<dim3(32, 7), 256>>>(KP_L1, 56);
    k_combine<3, 0><<<N_NODES, 128>>>(x, root[0], bias[0], lng[0], lnb[0], pXA);

    // ---- layer 2 (elu) — fp16 1-pass HMMA ----
    k_scatter_f16<<<N_NODES, 256>>>(pXA, ei, pHc + (size_t)1 * N_EDGES * HDIM);
    k_gemm_mma<<<dim3(32, KSPLIT), 256, GEMM_SMEM>>>(pBf2);
    k_combine<128, 1><<<N_NODES, 128>>>(pXA, root[1], bias[1], lng[1], lnb[1], pXB);

    // ---- layer 3 (leaky_relu) — fp16 1-pass HMMA ----
    k_scatter_f16<<<N_NODES, 256>>>(pXB, ei, pHc + (size_t)2 * N_EDGES * HDIM);
    k_gemm_mma<<<dim3(32, KSPLIT), 256, GEMM_SMEM>>>(pBf3);
    k_combine<128, 2><<<N_NODES, 128>>>(pXB, root[2], bias[2], lng[2], lnb[2], pXA);

    // ---- pooling + final linear ----
    k_pool<<<N_GRAPHS, 128>>>(pXA, ct, ls, lw, lb, out);
}